// round 13
// baseline (speedup 1.0000x reference)
#include <cuda_runtime.h>
#include <cuda_bf16.h>
#include <math.h>

#define GG 128
#define NN 512
#define NV (GG*NN)          // 65536 nodes
#define HH 128              // hidden/feature dim
#define EHALF 8192
#define EPGP 18432          // padded directed-edge stride per graph (4-aligned segments)
#define LL 5
#define CC 10

// Scratch (device globals: allocation-free per harness rules)
__device__ float    g_bufA[NV * HH];        // 32 MB fp32 h
__device__ unsigned g_bufH[NV * 64];        // 16 MB: h (or x) as packed bf16x2 for gather
__device__ unsigned g_Uh[NV * 64];          // 16 MB: U hi plane (bf16x2 k-pairs)
__device__ unsigned g_Ul[NV * 64];          // 16 MB: U lo plane
__device__ int      g_row_ptr[NV];
__device__ int      g_deg[NV];
__device__ int      g_edge_off[GG * EPGP];  // local src index * 32 (uint2-row offsets)
__device__ unsigned g_Wth[LL * HH * 64];    // W^T hi, packed bf16 k-pairs [l][n][kw]
__device__ unsigned g_Wtl[LL * HH * 64];    // W^T lo
__device__ float    g_part[GG * 8 * HH];    // readout partials

// ---------------------------------------------------------------- fused CSR build (4-aligned segments)
__global__ void __launch_bounds__(512) k_csr(const int* __restrict__ src,
                                             const int* __restrict__ dst) {
    __shared__ int cnt[NN];
    __shared__ int pos[NN];
    int g = blockIdx.x, t = threadIdx.x;
    cnt[t] = 0;
    __syncthreads();

    int base1 = g * EHALF;
    int base2 = GG * EHALF + g * EHALF;
    for (int i = t; i < EHALF; i += 512) {
        atomicAdd(&cnt[dst[base1 + i] & (NN - 1)], 1);
        atomicAdd(&cnt[dst[base2 + i] & (NN - 1)], 1);
    }
    __syncthreads();

    int c  = cnt[t];
    int p4 = (c + 3) & ~3;
    pos[t] = p4;
    __syncthreads();
    for (int off = 1; off < NN; off <<= 1) {
        int v = (t >= off) ? pos[t - off] : 0;
        __syncthreads();
        pos[t] += v;
        __syncthreads();
    }
    int startLocal = pos[t] - p4;
    g_row_ptr[g * NN + t] = g * EPGP + startLocal;
    g_deg[g * NN + t]     = c;
    cnt[t] = startLocal;
    __syncthreads();

    int* eout = g_edge_off + g * EPGP;
    for (int i = t; i < EHALF; i += 512) {
        int d = dst[base1 + i] & (NN - 1);
        int p = atomicAdd(&cnt[d], 1);
        eout[p] = (src[base1 + i] & (NN - 1)) * 32;
        d = dst[base2 + i] & (NN - 1);
        p = atomicAdd(&cnt[d], 1);
        eout[p] = (src[base2 + i] & (NN - 1)) * 32;
    }
}

// ---------------------------------------------------------------- W prep: transpose + bf16 hi/lo split
__global__ void k_prepw(const float* __restrict__ W) {
    int i = blockIdx.x * blockDim.x + threadIdx.x;
    if (i >= LL * HH * 64) return;
    int kw = i & 63;
    int n  = (i >> 6) & (HH - 1);
    int l  = i >> 13;
    const float* Wl = W + l * HH * HH;
    float w0 = Wl[(2 * kw) * HH + n];
    float w1 = Wl[(2 * kw + 1) * HH + n];
    __nv_bfloat162 h = __float22bfloat162_rn(make_float2(w0, w1));
    float2 hf = __bfloat1622float2(h);
    __nv_bfloat162 lo = __float22bfloat162_rn(make_float2(w0 - hf.x, w1 - hf.y));
    g_Wth[i] = *reinterpret_cast<unsigned*>(&h);
    g_Wtl[i] = *reinterpret_cast<unsigned*>(&lo);
}

// ---------------------------------------------------------------- x -> bf16 gather copy
__global__ void __launch_bounds__(256) k_prepx(const float* __restrict__ x) {
    int i = blockIdx.x * 256 + threadIdx.x;
    float4 v = ((const float4*)x)[i];
    __nv_bfloat162 a = __float22bfloat162_rn(make_float2(v.x, v.y));
    __nv_bfloat162 b = __float22bfloat162_rn(make_float2(v.z, v.w));
    uint2 w;
    w.x = *(unsigned*)&a; w.y = *(unsigned*)&b;
    ((uint2*)g_bufH)[i] = w;
}

// ---------------------------------------------------------------- packed f32x2 helpers
__device__ __forceinline__ unsigned long long pk2(float x, float y) {
    unsigned long long r;
    asm("mov.b64 %0, {%1, %2};" : "=l"(r) : "f"(x), "f"(y));
    return r;
}
__device__ __forceinline__ void addbf2(unsigned long long& a, unsigned w) {
    unsigned long long t;
    unsigned lo = w << 16, hi = w & 0xffff0000u;
    asm("mov.b64 %0, {%1, %2};" : "=l"(t) : "r"(lo), "r"(hi));
    asm("add.rn.f32x2 %0, %0, %1;" : "+l"(a) : "l"(t));
}
__device__ __forceinline__ void addx2(unsigned long long& a, unsigned long long b) {
    asm("add.rn.f32x2 %0, %0, %1;" : "+l"(a) : "l"(b));
}
__device__ __forceinline__ float2 unpk2(unsigned long long a) {
    float x, y;
    asm("mov.b64 {%0, %1}, %2;" : "=f"(x), "=f"(y) : "l"(a));
    return make_float2(x, y);
}

// ---------------------------------------------------------------- SpMM (bf16 gather, f32x2 accumulate)
// One warp per node; lane owns 4 feats. Offsets via int4 (aligned padded CSR).
// Self-term fp32 exact; output written as bf16 hi/lo planes.
__global__ void __launch_bounds__(256) k_spmm_bf(const float* __restrict__ xin,
                                                 const float* __restrict__ eps,
                                                 int layer) {
    const float* hin = (layer == 0) ? xin : g_bufA;

    int wid  = (blockIdx.x * blockDim.x + threadIdx.x) >> 5;
    int lane = threadIdx.x & 31;

    int g = wid >> 9;
    const uint2* hg2 = (const uint2*)g_bufH + (size_t)g * NN * 32;

    float e1 = 1.0f + __ldg(&eps[layer]);
    int base = wid * 32 + lane;

    float4 h0 = ((const float4*)hin)[base];
    // pair accumulators: A = feats {0,1}, B = feats {2,3}; dual set for MLP
    unsigned long long accA0 = pk2(e1 * h0.x, e1 * h0.y);
    unsigned long long accB0 = pk2(e1 * h0.z, e1 * h0.w);
    unsigned long long accA1 = pk2(0.f, 0.f);
    unsigned long long accB1 = pk2(0.f, 0.f);

    int e0 = g_row_ptr[wid];
    int d  = g_deg[wid];
    const int4* eo4 = (const int4*)(g_edge_off + e0);
    int n4 = d >> 2;

#pragma unroll 2
    for (int i = 0; i < n4; i++) {
        int4 o = eo4[i];
        uint2 v0 = hg2[o.x + lane];
        uint2 v1 = hg2[o.y + lane];
        uint2 v2 = hg2[o.z + lane];
        uint2 v3 = hg2[o.w + lane];
        addbf2(accA0, v0.x); addbf2(accB0, v0.y);
        addbf2(accA1, v1.x); addbf2(accB1, v1.y);
        addbf2(accA0, v2.x); addbf2(accB0, v2.y);
        addbf2(accA1, v3.x); addbf2(accB1, v3.y);
    }
    int rem = d & 3;
    const int* eo = g_edge_off + e0 + (n4 << 2);
    for (int i = 0; i < rem; i++) {
        uint2 v0 = hg2[eo[i] + lane];
        addbf2(accA0, v0.x); addbf2(accB0, v0.y);
    }
    addx2(accA0, accA1);
    addx2(accB0, accB1);
    float2 abxy = unpk2(accA0);
    float2 abzw = unpk2(accB0);
    float4 acc;
    acc.x = abxy.x; acc.y = abxy.y; acc.z = abzw.x; acc.w = abzw.y;

    __nv_bfloat162 hA = __float22bfloat162_rn(make_float2(acc.x, acc.y));
    __nv_bfloat162 hB = __float22bfloat162_rn(make_float2(acc.z, acc.w));
    float2 fA = __bfloat1622float2(hA);
    float2 fB = __bfloat1622float2(hB);
    __nv_bfloat162 lA = __float22bfloat162_rn(make_float2(acc.x - fA.x, acc.y - fA.y));
    __nv_bfloat162 lB = __float22bfloat162_rn(make_float2(acc.z - fB.x, acc.w - fB.y));
    uint2 hw, lw;
    hw.x = *(unsigned*)&hA; hw.y = *(unsigned*)&hB;
    lw.x = *(unsigned*)&lA; lw.y = *(unsigned*)&lB;
    ((uint2*)g_Uh)[base] = hw;
    ((uint2*)g_Ul)[base] = lw;
}

// ---------------------------------------------------------------- tensor-core GEMM + bias + relu (R11, verbatim)
// h = relu(U @ W_l + b_l). 3-pass bf16 split, fp32 accum. 256 thr, 2x64-row tiles,
// warp grid 2x4, 32x32 warp tiles, ldmatrix.x4 everywhere. U staged by pure uint4 copy.

#define SW 136   // bf16 elems per smem row (272 B stride, ldmatrix conflict-free)
#define SMEM_GEMM ((64*SW + 64*SW + HH*SW + HH*SW) * 2 + HH * 4)

#define MMA_BF16(C, A0, A1, A2, A3, B0, B1)                                      \
    asm volatile("mma.sync.aligned.m16n8k16.row.col.f32.bf16.bf16.f32 "          \
                 "{%0,%1,%2,%3}, {%4,%5,%6,%7}, {%8,%9}, {%0,%1,%2,%3};"         \
                 : "+f"(C[0]), "+f"(C[1]), "+f"(C[2]), "+f"(C[3])                \
                 : "r"(A0), "r"(A1), "r"(A2), "r"(A3), "r"(B0), "r"(B1))

#define LDMX4(R, addr)                                                           \
    asm volatile("ldmatrix.sync.aligned.m8n8.x4.shared.b16 {%0,%1,%2,%3}, [%4];" \
                 : "=r"(R[0]), "=r"(R[1]), "=r"(R[2]), "=r"(R[3]) : "r"(addr))

__global__ void __launch_bounds__(256) k_gemm_tc(const float* __restrict__ b,
                                                 int layer, int writeBF) {
    extern __shared__ char smem[];
    __nv_bfloat16* sUh = (__nv_bfloat16*)smem;
    __nv_bfloat16* sUl = sUh + 64 * SW;
    __nv_bfloat16* sWh = sUl + 64 * SW;
    __nv_bfloat16* sWl = sWh + HH * SW;
    float*         sB  = (float*)(sWl + HH * SW);

    int tid = threadIdx.x;

    // ---- stage W hi/lo once (packed bf16 [n][k]) ----
    {
        const uint4* wh4 = (const uint4*)(g_Wth + layer * HH * 64);
        const uint4* wl4 = (const uint4*)(g_Wtl + layer * HH * 64);
#pragma unroll
        for (int k = 0; k < 8; k++) {
            int q = tid + k * 256;            // 2048 uint4
            int n = q >> 4, cw = (q & 15) * 4;
            *(uint4*)(sWh + n * SW + cw * 2) = wh4[q];
            *(uint4*)(sWl + n * SW + cw * 2) = wl4[q];
        }
    }
    if (tid < HH) sB[tid] = b[layer * HH + tid];

    int warp = tid >> 5, lane = tid & 31;
    int wm = warp & 1, wn = warp >> 1;
    int rw = wm * 32, nw = wn * 32;

    // ldmatrix lane addressing
    int lb = lane >> 3, lr = lane & 7;
    int a_row = (lb & 1) * 8 + lr;
    int a_k   = (lb >> 1) * 8;
    int b_n   = (lb >> 1) * 8 + lr;
    int b_k   = (lb & 1) * 8;

    unsigned aH[2], aL[2], bH[2], bL[2];
#pragma unroll
    for (int mt = 0; mt < 2; mt++) {
        int row = rw + mt * 16 + a_row;
        aH[mt] = (unsigned)__cvta_generic_to_shared(sUh + row * SW + a_k);
        aL[mt] = (unsigned)__cvta_generic_to_shared(sUl + row * SW + a_k);
    }
#pragma unroll
    for (int jp = 0; jp < 2; jp++) {
        int n = nw + jp * 16 + b_n;
        bH[jp] = (unsigned)__cvta_generic_to_shared(sWh + n * SW + b_k);
        bL[jp] = (unsigned)__cvta_generic_to_shared(sWl + n * SW + b_k);
    }

    int g2 = lane >> 2, tg = lane & 3;
    unsigned* sUhU = (unsigned*)sUh;

#pragma unroll 1
    for (int tile = 0; tile < 2; tile++) {
        int rowBase = blockIdx.x * 128 + tile * 64;

        __syncthreads();   // W/bias ready (tile 0); prior copy-out done (tile 1)

        // ---- stage U: pure uint4 copy of prebuilt bf16 planes ----
        {
            const uint4* uh4 = (const uint4*)(g_Uh + (size_t)rowBase * 64);
            const uint4* ul4 = (const uint4*)(g_Ul + (size_t)rowBase * 64);
#pragma unroll
            for (int k = 0; k < 4; k++) {
                int q = tid + k * 256;        // 1024 uint4 per plane
                int r = q >> 4, c4 = q & 15;
                *(uint4*)((unsigned*)sUh + r * 68 + c4 * 4) = uh4[q];
                *(uint4*)((unsigned*)sUl + r * 68 + c4 * 4) = ul4[q];
            }
        }
        __syncthreads();

        float acc[2][4][4];
#pragma unroll
        for (int mt = 0; mt < 2; mt++)
#pragma unroll
            for (int j = 0; j < 4; j++)
#pragma unroll
                for (int q = 0; q < 4; q++) acc[mt][j][q] = 0.f;

#pragma unroll
        for (int ks = 0; ks < 8; ks++) {
            unsigned ko = (unsigned)ks * 32;  // 16 bf16 = 32 bytes
            unsigned Ah[2][4], Al[2][4];
            LDMX4(Ah[0], aH[0] + ko); LDMX4(Ah[1], aH[1] + ko);
            LDMX4(Al[0], aL[0] + ko); LDMX4(Al[1], aL[1] + ko);
#pragma unroll
            for (int jp = 0; jp < 2; jp++) {
                unsigned Bh[4], Bl[4];
                LDMX4(Bh, bH[jp] + ko);
                LDMX4(Bl, bL[jp] + ko);
#pragma unroll
                for (int mt = 0; mt < 2; mt++) {
#pragma unroll
                    for (int jj = 0; jj < 2; jj++) {
                        int j = jp * 2 + jj;
                        MMA_BF16(acc[mt][j], Ah[mt][0], Ah[mt][1], Ah[mt][2], Ah[mt][3],
                                 Bh[jj * 2], Bh[jj * 2 + 1]);
                        MMA_BF16(acc[mt][j], Al[mt][0], Al[mt][1], Al[mt][2], Al[mt][3],
                                 Bh[jj * 2], Bh[jj * 2 + 1]);
                        MMA_BF16(acc[mt][j], Ah[mt][0], Ah[mt][1], Ah[mt][2], Ah[mt][3],
                                 Bl[jj * 2], Bl[jj * 2 + 1]);
                    }
                }
            }
        }

        // ---- epilogue: bias + relu; fp32 h to g_bufA; bf16 packs kept in regs ----
        unsigned pk[2][4][2];
#pragma unroll
        for (int mt = 0; mt < 2; mt++) {
            int rA = rowBase + rw + mt * 16 + g2;
            int rB = rA + 8;
#pragma unroll
            for (int j = 0; j < 4; j++) {
                int c = nw + j * 8 + 2 * tg;
                float b0 = sB[c], b1 = sB[c + 1];
                float2 oA, oB;
                oA.x = fmaxf(acc[mt][j][0] + b0, 0.f);
                oA.y = fmaxf(acc[mt][j][1] + b1, 0.f);
                oB.x = fmaxf(acc[mt][j][2] + b0, 0.f);
                oB.y = fmaxf(acc[mt][j][3] + b1, 0.f);
                *(float2*)(g_bufA + (size_t)rA * HH + c) = oA;
                *(float2*)(g_bufA + (size_t)rB * HH + c) = oB;
                __nv_bfloat162 pA = __float22bfloat162_rn(oA);
                __nv_bfloat162 pB = __float22bfloat162_rn(oB);
                pk[mt][j][0] = *(unsigned*)&pA;
                pk[mt][j][1] = *(unsigned*)&pB;
            }
        }

        if (writeBF) {
            __syncthreads();    // all ldmatrix reads of sUh done
#pragma unroll
            for (int mt = 0; mt < 2; mt++) {
                int rloc = rw + mt * 16 + g2;
#pragma unroll
                for (int j = 0; j < 4; j++) {
                    int ch = (nw >> 1) + j * 4 + tg;
                    sUhU[rloc * 68 + ch]       = pk[mt][j][0];
                    sUhU[(rloc + 8) * 68 + ch] = pk[mt][j][1];
                }
            }
            __syncthreads();
#pragma unroll
            for (int k = 0; k < 4; k++) {
                int q = tid + k * 256;
                int r = q >> 4, c4 = q & 15;
                ((uint4*)g_bufH)[(size_t)(rowBase + r) * 16 + c4] =
                    *(uint4*)((unsigned*)sUh + r * 68 + c4 * 4);
            }
        }
    }
}

// ---------------------------------------------------------------- readout stage 1: partial node sums
__global__ void __launch_bounds__(128) k_sum() {
    const float* h = g_bufA;
    int g = blockIdx.x >> 3, p = blockIdx.x & 7;
    int t = threadIdx.x;
    const float* base = h + (size_t)g * NN * HH + p * 64 * HH + t;
    float s0 = 0.f, s1 = 0.f;
#pragma unroll 8
    for (int r = 0; r < 64; r += 2) {
        s0 += base[r * HH];
        s1 += base[(r + 1) * HH];
    }
    g_part[(g * 8 + p) * HH + t] = s0 + s1;
}

// ---------------------------------------------------------------- readout stage 2: FCs + softmax
__global__ void __launch_bounds__(128) k_fc(const float* __restrict__ fc1w,
                                            const float* __restrict__ fc1b,
                                            const float* __restrict__ fc2w,
                                            const float* __restrict__ fc2b,
                                            float* __restrict__ out) {
    __shared__ float hg[HH];
    __shared__ float a1[HH];
    __shared__ float z[CC];
    __shared__ float ez[CC];

    int g = blockIdx.x;
    int t = threadIdx.x;

    float s = 0.f;
#pragma unroll
    for (int p = 0; p < 8; p++) s += g_part[(g * 8 + p) * HH + t];
    hg[t] = s;
    __syncthreads();

    {
        float acc = fc1b[t];
        for (int k = 0; k < HH; k++) acc += hg[k] * __ldg(&fc1w[k * HH + t]);
        a1[t] = fmaxf(acc, 0.f);
    }
    __syncthreads();

    if (t < CC) {
        float acc = fc2b[t];
        for (int k = 0; k < HH; k++) acc += a1[k] * __ldg(&fc2w[k * CC + t]);
        z[t] = acc;
    }
    __syncthreads();

    if (t < CC) {
        float m = z[0];
#pragma unroll
        for (int j = 1; j < CC; j++) m = fmaxf(m, z[j]);
        ez[t] = expf(z[t] - m);
    }
    __syncthreads();

    if (t < CC) {
        float ssum = 0.f;
#pragma unroll
        for (int j = 0; j < CC; j++) ssum += ez[j];
        out[g * CC + t] = ez[t] / ssum;
    }
}

// ---------------------------------------------------------------- launch
extern "C" void kernel_launch(void* const* d_in, const int* in_sizes, int n_in,
                              void* d_out, int out_size) {
    const float* x    = (const float*)d_in[0];
    const float* eps  = (const float*)d_in[1];
    const float* W    = (const float*)d_in[2];
    const float* b    = (const float*)d_in[3];
    const float* fc1w = (const float*)d_in[4];
    const float* fc1b = (const float*)d_in[5];
    const float* fc2w = (const float*)d_in[6];
    const float* fc2b = (const float*)d_in[7];
    const int*   src  = (const int*)d_in[8];
    const int*   dst  = (const int*)d_in[9];
    float* out = (float*)d_out;

    cudaFuncSetAttribute(k_gemm_tc, cudaFuncAttributeMaxDynamicSharedMemorySize,
                         SMEM_GEMM);

    k_csr<<<GG, 512>>>(src, dst);
    k_prepw<<<(LL * HH * 64 + 255) / 256, 256>>>(W);
    k_prepx<<<NV * 32 / 256, 256>>>(x);

    for (int l = 0; l < LL; l++) {
        k_spmm_bf<<<NV / 8, 256>>>(x, eps, l);
        k_gemm_tc<<<NV / 128, 256, SMEM_GEMM>>>(b, l, (l < LL - 1) ? 1 : 0);
    }

    k_sum<<<GG * 8, 128>>>();
    k_fc<<<GG, 128>>>(fc1w, fc1b, fc2w, fc2b, out);
}

// round 14
// speedup vs baseline: 1.1392x; 1.1392x over previous
#include <cuda_runtime.h>
#include <cuda_bf16.h>
#include <math.h>

#define GG 128
#define NN 512
#define NV (GG*NN)          // 65536 nodes
#define HH 128              // hidden/feature dim
#define EE 2097152          // directed edges
#define EHALF 8192
#define EPG 16384           // directed edges per graph
#define LL 5
#define CC 10

// Scratch (device globals: allocation-free per harness rules)
__device__ float    g_bufA[NV * HH];        // 32 MB fp32 ping
__device__ float    g_bufB[NV * HH];        // 32 MB fp32 pong
__device__ unsigned g_bufH[NV * 64];        // 16 MB: h (or x) as packed bf16x2 for gather
__device__ int      g_row_ptr[NV + 1];
__device__ int      g_edge_off[EE];         // local src index * 32 (uint2-row offsets)
__device__ unsigned g_Wth[LL * HH * 64];    // W^T hi, packed bf16 k-pairs [l][n][kw]
__device__ unsigned g_Wtl[LL * HH * 64];    // W^T lo
__device__ float    g_part[GG * 8 * HH];    // readout partials

// ---------------------------------------------------------------- fused CSR build (R10 verbatim)
__global__ void __launch_bounds__(512) k_csr(const int* __restrict__ src,
                                             const int* __restrict__ dst) {
    __shared__ int cnt[NN];
    __shared__ int pos[NN];
    int g = blockIdx.x, t = threadIdx.x;
    cnt[t] = 0;
    __syncthreads();

    int base1 = g * EHALF;
    int base2 = GG * EHALF + g * EHALF;
    for (int i = t; i < EHALF; i += 512) {
        atomicAdd(&cnt[dst[base1 + i] & (NN - 1)], 1);
        atomicAdd(&cnt[dst[base2 + i] & (NN - 1)], 1);
    }
    __syncthreads();

    int c = cnt[t];
    pos[t] = c;
    __syncthreads();
    for (int off = 1; off < NN; off <<= 1) {
        int v = (t >= off) ? pos[t - off] : 0;
        __syncthreads();
        pos[t] += v;
        __syncthreads();
    }
    int startLocal = pos[t] - c;
    g_row_ptr[g * NN + t] = g * EPG + startLocal;
    cnt[t] = startLocal;
    if (g == 0 && t == 0) g_row_ptr[NV] = EE;
    __syncthreads();

    int* eout = g_edge_off + g * EPG;
    for (int i = t; i < EHALF; i += 512) {
        int d = dst[base1 + i] & (NN - 1);
        int p = atomicAdd(&cnt[d], 1);
        eout[p] = (src[base1 + i] & (NN - 1)) * 32;
        d = dst[base2 + i] & (NN - 1);
        p = atomicAdd(&cnt[d], 1);
        eout[p] = (src[base2 + i] & (NN - 1)) * 32;
    }
}

// ---------------------------------------------------------------- W prep: transpose + bf16 hi/lo split
__global__ void k_prepw(const float* __restrict__ W) {
    int i = blockIdx.x * blockDim.x + threadIdx.x;
    if (i >= LL * HH * 64) return;
    int kw = i & 63;
    int n  = (i >> 6) & (HH - 1);
    int l  = i >> 13;
    const float* Wl = W + l * HH * HH;
    float w0 = Wl[(2 * kw) * HH + n];
    float w1 = Wl[(2 * kw + 1) * HH + n];
    __nv_bfloat162 h = __float22bfloat162_rn(make_float2(w0, w1));
    float2 hf = __bfloat1622float2(h);
    __nv_bfloat162 lo = __float22bfloat162_rn(make_float2(w0 - hf.x, w1 - hf.y));
    g_Wth[i] = *reinterpret_cast<unsigned*>(&h);
    g_Wtl[i] = *reinterpret_cast<unsigned*>(&lo);
}

// ---------------------------------------------------------------- x -> bf16 gather copy
__global__ void __launch_bounds__(256) k_prepx(const float* __restrict__ x) {
    int i = blockIdx.x * 256 + threadIdx.x;
    float4 v = ((const float4*)x)[i];
    __nv_bfloat162 a = __float22bfloat162_rn(make_float2(v.x, v.y));
    __nv_bfloat162 b = __float22bfloat162_rn(make_float2(v.z, v.w));
    uint2 w;
    w.x = *(unsigned*)&a; w.y = *(unsigned*)&b;
    ((uint2*)g_bufH)[i] = w;
}

// ---------------------------------------------------------------- SpMM (R10 body: bf16 gather, fp32 scalar adds)
// One warp per node; lane owns 4 feats (one uint2). Self-term fp32 exact from
// fp32 buffer; neighbor terms gathered bf16, converted by exact 16-bit shift.
__global__ void __launch_bounds__(256) k_spmm_bf(const float* __restrict__ xin,
                                                 const float* __restrict__ eps,
                                                 int layer, int ssel, int dsel) {
    const float* hin  = (ssel == 0) ? xin : (ssel == 1 ? g_bufA : g_bufB);
    float*       uout = (dsel == 1) ? g_bufA : g_bufB;

    int wid  = (blockIdx.x * blockDim.x + threadIdx.x) >> 5;
    int lane = threadIdx.x & 31;

    int g = wid >> 9;
    const uint2* hg2 = (const uint2*)g_bufH + (size_t)g * NN * 32;

    float e1 = 1.0f + __ldg(&eps[layer]);
    int base = wid * 32 + lane;

    float4 h0 = ((const float4*)hin)[base];
    float4 acc;
    acc.x = e1 * h0.x; acc.y = e1 * h0.y; acc.z = e1 * h0.z; acc.w = e1 * h0.w;
    float4 acc1; acc1.x = 0.f; acc1.y = 0.f; acc1.z = 0.f; acc1.w = 0.f;

    int e    = g_row_ptr[wid];
    int eend = g_row_ptr[wid + 1];

    for (; e + 4 <= eend; e += 4) {
        int o0 = g_edge_off[e + 0];
        int o1 = g_edge_off[e + 1];
        int o2 = g_edge_off[e + 2];
        int o3 = g_edge_off[e + 3];
        uint2 v0 = hg2[o0 + lane];
        uint2 v1 = hg2[o1 + lane];
        uint2 v2 = hg2[o2 + lane];
        uint2 v3 = hg2[o3 + lane];
        acc.x  += __uint_as_float(v0.x << 16);
        acc.y  += __uint_as_float(v0.x & 0xffff0000u);
        acc.z  += __uint_as_float(v0.y << 16);
        acc.w  += __uint_as_float(v0.y & 0xffff0000u);
        acc1.x += __uint_as_float(v1.x << 16);
        acc1.y += __uint_as_float(v1.x & 0xffff0000u);
        acc1.z += __uint_as_float(v1.y << 16);
        acc1.w += __uint_as_float(v1.y & 0xffff0000u);
        acc.x  += __uint_as_float(v2.x << 16);
        acc.y  += __uint_as_float(v2.x & 0xffff0000u);
        acc.z  += __uint_as_float(v2.y << 16);
        acc.w  += __uint_as_float(v2.y & 0xffff0000u);
        acc1.x += __uint_as_float(v3.x << 16);
        acc1.y += __uint_as_float(v3.x & 0xffff0000u);
        acc1.z += __uint_as_float(v3.y << 16);
        acc1.w += __uint_as_float(v3.y & 0xffff0000u);
    }
    for (; e < eend; e++) {
        uint2 v0 = hg2[g_edge_off[e] + lane];
        acc.x += __uint_as_float(v0.x << 16);
        acc.y += __uint_as_float(v0.x & 0xffff0000u);
        acc.z += __uint_as_float(v0.y << 16);
        acc.w += __uint_as_float(v0.y & 0xffff0000u);
    }
    acc.x += acc1.x; acc.y += acc1.y; acc.z += acc1.z; acc.w += acc1.w;
    ((float4*)uout)[base] = acc;
}

// ---------------------------------------------------------------- tensor-core GEMM + bias + relu
// h = relu(U @ W_l + b_l), in place. 3-pass bf16 split, fp32 accum.
// R7 config: 256 thr, warp grid 2x4 (32x32 warp tiles), two 64-row tiles per CTA,
// W staged once. U staged fp32 -> bf16 hi/lo conversion (R7-measured).
// Epilogue: fp32 in place + coalesced bf16 copy via smem bounce (R11-measured).

#define SW 136   // bf16 elems per smem row (272 B stride, ldmatrix conflict-free)
#define SMEM_GEMM ((64*SW + 64*SW + HH*SW + HH*SW) * 2 + HH * 4)

#define MMA_BF16(C, A0, A1, A2, A3, B0, B1)                                      \
    asm volatile("mma.sync.aligned.m16n8k16.row.col.f32.bf16.bf16.f32 "          \
                 "{%0,%1,%2,%3}, {%4,%5,%6,%7}, {%8,%9}, {%0,%1,%2,%3};"         \
                 : "+f"(C[0]), "+f"(C[1]), "+f"(C[2]), "+f"(C[3])                \
                 : "r"(A0), "r"(A1), "r"(A2), "r"(A3), "r"(B0), "r"(B1))

#define LDMX4(R, addr)                                                           \
    asm volatile("ldmatrix.sync.aligned.m8n8.x4.shared.b16 {%0,%1,%2,%3}, [%4];" \
                 : "=r"(R[0]), "=r"(R[1]), "=r"(R[2]), "=r"(R[3]) : "r"(addr))

__global__ void __launch_bounds__(256) k_gemm_tc(const float* __restrict__ b,
                                                 int layer, int bufsel, int writeBF) {
    float* u = (bufsel == 1) ? g_bufA : g_bufB;

    extern __shared__ char smem[];
    __nv_bfloat16* sUh = (__nv_bfloat16*)smem;
    __nv_bfloat16* sUl = sUh + 64 * SW;
    __nv_bfloat16* sWh = sUl + 64 * SW;
    __nv_bfloat16* sWl = sWh + HH * SW;
    float*         sB  = (float*)(sWl + HH * SW);

    int tid = threadIdx.x;

    // ---- stage W hi/lo once (packed bf16 [n][k]) ----
    {
        const uint4* wh4 = (const uint4*)(g_Wth + layer * HH * 64);
        const uint4* wl4 = (const uint4*)(g_Wtl + layer * HH * 64);
#pragma unroll
        for (int k = 0; k < 8; k++) {
            int q = tid + k * 256;            // 2048 uint4
            int n = q >> 4, cw = (q & 15) * 4;
            *(uint4*)(sWh + n * SW + cw * 2) = wh4[q];
            *(uint4*)(sWl + n * SW + cw * 2) = wl4[q];
        }
    }
    if (tid < HH) sB[tid] = b[layer * HH + tid];

    int warp = tid >> 5, lane = tid & 31;
    int wm = warp & 1, wn = warp >> 1;
    int rw = wm * 32, nw = wn * 32;

    // ldmatrix lane addressing
    int lb = lane >> 3, lr = lane & 7;
    int a_row = (lb & 1) * 8 + lr;
    int a_k   = (lb >> 1) * 8;
    int b_n   = (lb >> 1) * 8 + lr;
    int b_k   = (lb & 1) * 8;

    unsigned aH[2], aL[2], bH[2], bL[2];
#pragma unroll
    for (int mt = 0; mt < 2; mt++) {
        int row = rw + mt * 16 + a_row;
        aH[mt] = (unsigned)__cvta_generic_to_shared(sUh + row * SW + a_k);
        aL[mt] = (unsigned)__cvta_generic_to_shared(sUl + row * SW + a_k);
    }
#pragma unroll
    for (int jp = 0; jp < 2; jp++) {
        int n = nw + jp * 16 + b_n;
        bH[jp] = (unsigned)__cvta_generic_to_shared(sWh + n * SW + b_k);
        bL[jp] = (unsigned)__cvta_generic_to_shared(sWl + n * SW + b_k);
    }

    int g2 = lane >> 2, tg = lane & 3;
    unsigned* sUhU = (unsigned*)sUh;

#pragma unroll 1
    for (int tile = 0; tile < 2; tile++) {
        int rowBase = blockIdx.x * 128 + tile * 64;

        __syncthreads();   // W/bias ready (tile 0); prior tile's smem reads done (tile 1)

        // ---- stage U (fp32 -> bf16 hi/lo planes), 64 rows ----
        {
            const float4* u4 = (const float4*)(u + (size_t)rowBase * HH);
#pragma unroll
            for (int k = 0; k < 8; k++) {
                int q = tid + k * 256;        // 2048 float4
                int r = q >> 5, c = (q & 31) * 4;
                float4 v = u4[q];
                __nv_bfloat162 h01 = __float22bfloat162_rn(make_float2(v.x, v.y));
                __nv_bfloat162 h23 = __float22bfloat162_rn(make_float2(v.z, v.w));
                float2 f01 = __bfloat1622float2(h01);
                float2 f23 = __bfloat1622float2(h23);
                __nv_bfloat162 l01 = __float22bfloat162_rn(make_float2(v.x - f01.x, v.y - f01.y));
                __nv_bfloat162 l23 = __float22bfloat162_rn(make_float2(v.z - f23.x, v.w - f23.y));
                uint2 hw, lw;
                hw.x = *(unsigned*)&h01; hw.y = *(unsigned*)&h23;
                lw.x = *(unsigned*)&l01; lw.y = *(unsigned*)&l23;
                *(uint2*)(sUh + r * SW + c) = hw;
                *(uint2*)(sUl + r * SW + c) = lw;
            }
        }
        __syncthreads();

        float acc[2][4][4];
#pragma unroll
        for (int mt = 0; mt < 2; mt++)
#pragma unroll
            for (int j = 0; j < 4; j++)
#pragma unroll
                for (int q = 0; q < 4; q++) acc[mt][j][q] = 0.f;

#pragma unroll
        for (int ks = 0; ks < 8; ks++) {
            unsigned ko = (unsigned)ks * 32;  // 16 bf16 = 32 bytes
            unsigned Ah[2][4], Al[2][4];
            LDMX4(Ah[0], aH[0] + ko); LDMX4(Ah[1], aH[1] + ko);
            LDMX4(Al[0], aL[0] + ko); LDMX4(Al[1], aL[1] + ko);
#pragma unroll
            for (int jp = 0; jp < 2; jp++) {
                unsigned Bh[4], Bl[4];
                LDMX4(Bh, bH[jp] + ko);
                LDMX4(Bl, bL[jp] + ko);
#pragma unroll
                for (int mt = 0; mt < 2; mt++) {
#pragma unroll
                    for (int jj = 0; jj < 2; jj++) {
                        int j = jp * 2 + jj;
                        MMA_BF16(acc[mt][j], Ah[mt][0], Ah[mt][1], Ah[mt][2], Ah[mt][3],
                                 Bh[jj * 2], Bh[jj * 2 + 1]);
                        MMA_BF16(acc[mt][j], Al[mt][0], Al[mt][1], Al[mt][2], Al[mt][3],
                                 Bh[jj * 2], Bh[jj * 2 + 1]);
                        MMA_BF16(acc[mt][j], Ah[mt][0], Ah[mt][1], Ah[mt][2], Ah[mt][3],
                                 Bl[jj * 2], Bl[jj * 2 + 1]);
                    }
                }
            }
        }

        // ---- epilogue: bias + relu; fp32 in place; bf16 packs kept in regs ----
        unsigned pk[2][4][2];
#pragma unroll
        for (int mt = 0; mt < 2; mt++) {
            int rA = rowBase + rw + mt * 16 + g2;
            int rB = rA + 8;
#pragma unroll
            for (int j = 0; j < 4; j++) {
                int c = nw + j * 8 + 2 * tg;
                float b0 = sB[c], b1 = sB[c + 1];
                float2 oA, oB;
                oA.x = fmaxf(acc[mt][j][0] + b0, 0.f);
                oA.y = fmaxf(acc[mt][j][1] + b1, 0.f);
                oB.x = fmaxf(acc[mt][j][2] + b0, 0.f);
                oB.y = fmaxf(acc[mt][j][3] + b1, 0.f);
                *(float2*)(u + (size_t)rA * HH + c) = oA;
                *(float2*)(u + (size_t)rB * HH + c) = oB;
                __nv_bfloat162 pA = __float22bfloat162_rn(oA);
                __nv_bfloat162 pB = __float22bfloat162_rn(oB);
                pk[mt][j][0] = *(unsigned*)&pA;
                pk[mt][j][1] = *(unsigned*)&pB;
            }
        }

        if (writeBF) {
            __syncthreads();    // all ldmatrix reads of sUh done
#pragma unroll
            for (int mt = 0; mt < 2; mt++) {
                int rloc = rw + mt * 16 + g2;
#pragma unroll
                for (int j = 0; j < 4; j++) {
                    int ch = (nw >> 1) + j * 4 + tg;
                    sUhU[rloc * 68 + ch]       = pk[mt][j][0];
                    sUhU[(rloc + 8) * 68 + ch] = pk[mt][j][1];
                }
            }
            __syncthreads();
#pragma unroll
            for (int k = 0; k < 4; k++) {
                int q = tid + k * 256;        // 1024 uint4
                int r = q >> 4, c4 = q & 15;
                ((uint4*)g_bufH)[(size_t)(rowBase + r) * 16 + c4] =
                    *(uint4*)((unsigned*)sUh + r * 68 + c4 * 4);
            }
        }
    }
}

// ---------------------------------------------------------------- readout stage 1: partial node sums
__global__ void __launch_bounds__(128) k_sum(int bufsel) {
    const float* h = (bufsel == 1) ? g_bufA : g_bufB;
    int g = blockIdx.x >> 3, p = blockIdx.x & 7;
    int t = threadIdx.x;
    const float* base = h + (size_t)g * NN * HH + p * 64 * HH + t;
    float s0 = 0.f, s1 = 0.f;
#pragma unroll 8
    for (int r = 0; r < 64; r += 2) {
        s0 += base[r * HH];
        s1 += base[(r + 1) * HH];
    }
    g_part[(g * 8 + p) * HH + t] = s0 + s1;
}

// ---------------------------------------------------------------- readout stage 2: FCs + softmax
__global__ void __launch_bounds__(128) k_fc(const float* __restrict__ fc1w,
                                            const float* __restrict__ fc1b,
                                            const float* __restrict__ fc2w,
                                            const float* __restrict__ fc2b,
                                            float* __restrict__ out) {
    __shared__ float hg[HH];
    __shared__ float a1[HH];
    __shared__ float z[CC];
    __shared__ float ez[CC];

    int g = blockIdx.x;
    int t = threadIdx.x;

    float s = 0.f;
#pragma unroll
    for (int p = 0; p < 8; p++) s += g_part[(g * 8 + p) * HH + t];
    hg[t] = s;
    __syncthreads();

    {
        float acc = fc1b[t];
        for (int k = 0; k < HH; k++) acc += hg[k] * __ldg(&fc1w[k * HH + t]);
        a1[t] = fmaxf(acc, 0.f);
    }
    __syncthreads();

    if (t < CC) {
        float acc = fc2b[t];
        for (int k = 0; k < HH; k++) acc += a1[k] * __ldg(&fc2w[k * CC + t]);
        z[t] = acc;
    }
    __syncthreads();

    if (t < CC) {
        float m = z[0];
#pragma unroll
        for (int j = 1; j < CC; j++) m = fmaxf(m, z[j]);
        ez[t] = expf(z[t] - m);
    }
    __syncthreads();

    if (t < CC) {
        float ssum = 0.f;
#pragma unroll
        for (int j = 0; j < CC; j++) ssum += ez[j];
        out[g * CC + t] = ez[t] / ssum;
    }
}

// ---------------------------------------------------------------- launch
extern "C" void kernel_launch(void* const* d_in, const int* in_sizes, int n_in,
                              void* d_out, int out_size) {
    const float* x    = (const float*)d_in[0];
    const float* eps  = (const float*)d_in[1];
    const float* W    = (const float*)d_in[2];
    const float* b    = (const float*)d_in[3];
    const float* fc1w = (const float*)d_in[4];
    const float* fc1b = (const float*)d_in[5];
    const float* fc2w = (const float*)d_in[6];
    const float* fc2b = (const float*)d_in[7];
    const int*   src  = (const int*)d_in[8];
    const int*   dst  = (const int*)d_in[9];
    float* out = (float*)d_out;

    cudaFuncSetAttribute(k_gemm_tc, cudaFuncAttributeMaxDynamicSharedMemorySize,
                         SMEM_GEMM);

    k_csr<<<GG, 512>>>(src, dst);
    k_prepw<<<(LL * HH * 64 + 255) / 256, 256>>>(W);
    k_prepx<<<NV * 32 / 256, 256>>>(x);

    // src: 0=x, 1=bufA, 2=bufB. dst/bufsel: 1=bufA, 2=bufB. Final h in A.
    const int ssel[LL] = {0, 1, 2, 1, 2};
    const int dsel[LL] = {1, 2, 1, 2, 1};
    for (int l = 0; l < LL; l++) {
        k_spmm_bf<<<NV / 8, 256>>>(x, eps, l, ssel[l], dsel[l]);
        k_gemm_tc<<<NV / 128, 256, SMEM_GEMM>>>(b, l, dsel[l], (l < LL - 1) ? 1 : 0);
    }

    k_sum<<<GG * 8, 128>>>(1);
    k_fc<<<GG, 128>>>(fc1w, fc1b, fc2w, fc2b, out);
}

// round 15
// speedup vs baseline: 1.1445x; 1.0047x over previous
#include <cuda_runtime.h>
#include <cuda_bf16.h>
#include <math.h>

#define GG 128
#define NN 512
#define NV (GG*NN)          // 65536 nodes
#define HH 128              // hidden/feature dim
#define EE 2097152          // directed edges
#define EHALF 8192
#define EPG 16384           // directed edges per graph
#define LL 5
#define CC 10

// Scratch (device globals: allocation-free per harness rules)
__device__ float    g_bufA[NV * HH];        // 32 MB fp32 h (single buffer; kernels serialize)
__device__ unsigned g_bufH[NV * 64];        // 16 MB: h (or x) as packed bf16x2 for gather
__device__ unsigned g_Uh[NV * 64];          // 16 MB: U hi plane (bf16x2 k-pairs)
__device__ unsigned g_Ul[NV * 64];          // 16 MB: U lo plane
__device__ int      g_row_ptr[NV + 1];
__device__ int      g_edge_off[EE];         // local src index * 32 (uint2-row offsets)
__device__ unsigned g_Wth[LL * HH * 64];    // W^T hi, packed bf16 k-pairs [l][n][kw]
__device__ unsigned g_Wtl[LL * HH * 64];    // W^T lo
__device__ float    g_part[GG * 8 * HH];    // readout partials

// ---------------------------------------------------------------- fused CSR build (R14 verbatim)
__global__ void __launch_bounds__(512) k_csr(const int* __restrict__ src,
                                             const int* __restrict__ dst) {
    __shared__ int cnt[NN];
    __shared__ int pos[NN];
    int g = blockIdx.x, t = threadIdx.x;
    cnt[t] = 0;
    __syncthreads();

    int base1 = g * EHALF;
    int base2 = GG * EHALF + g * EHALF;
    for (int i = t; i < EHALF; i += 512) {
        atomicAdd(&cnt[dst[base1 + i] & (NN - 1)], 1);
        atomicAdd(&cnt[dst[base2 + i] & (NN - 1)], 1);
    }
    __syncthreads();

    int c = cnt[t];
    pos[t] = c;
    __syncthreads();
    for (int off = 1; off < NN; off <<= 1) {
        int v = (t >= off) ? pos[t - off] : 0;
        __syncthreads();
        pos[t] += v;
        __syncthreads();
    }
    int startLocal = pos[t] - c;
    g_row_ptr[g * NN + t] = g * EPG + startLocal;
    cnt[t] = startLocal;
    if (g == 0 && t == 0) g_row_ptr[NV] = EE;
    __syncthreads();

    int* eout = g_edge_off + g * EPG;
    for (int i = t; i < EHALF; i += 512) {
        int d = dst[base1 + i] & (NN - 1);
        int p = atomicAdd(&cnt[d], 1);
        eout[p] = (src[base1 + i] & (NN - 1)) * 32;
        d = dst[base2 + i] & (NN - 1);
        p = atomicAdd(&cnt[d], 1);
        eout[p] = (src[base2 + i] & (NN - 1)) * 32;
    }
}

// ---------------------------------------------------------------- W prep: transpose + bf16 hi/lo split
__global__ void k_prepw(const float* __restrict__ W) {
    int i = blockIdx.x * blockDim.x + threadIdx.x;
    if (i >= LL * HH * 64) return;
    int kw = i & 63;
    int n  = (i >> 6) & (HH - 1);
    int l  = i >> 13;
    const float* Wl = W + l * HH * HH;
    float w0 = Wl[(2 * kw) * HH + n];
    float w1 = Wl[(2 * kw + 1) * HH + n];
    __nv_bfloat162 h = __float22bfloat162_rn(make_float2(w0, w1));
    float2 hf = __bfloat1622float2(h);
    __nv_bfloat162 lo = __float22bfloat162_rn(make_float2(w0 - hf.x, w1 - hf.y));
    g_Wth[i] = *reinterpret_cast<unsigned*>(&h);
    g_Wtl[i] = *reinterpret_cast<unsigned*>(&lo);
}

// ---------------------------------------------------------------- x -> bf16 gather copy
__global__ void __launch_bounds__(256) k_prepx(const float* __restrict__ x) {
    int i = blockIdx.x * 256 + threadIdx.x;
    float4 v = ((const float4*)x)[i];
    __nv_bfloat162 a = __float22bfloat162_rn(make_float2(v.x, v.y));
    __nv_bfloat162 b = __float22bfloat162_rn(make_float2(v.z, v.w));
    uint2 w;
    w.x = *(unsigned*)&a; w.y = *(unsigned*)&b;
    ((uint2*)g_bufH)[i] = w;
}

// ---------------------------------------------------------------- SpMM (R14 body; plane-split output)
// One warp per node; lane owns 4 feats (one uint2). Self-term fp32 exact from
// fp32 buffer; neighbor terms gathered bf16 (exact 16-bit shift), fp32 accum.
// Output: U as bf16 hi/lo planes (exact hi+lo split of fp32 acc).
__global__ void __launch_bounds__(256) k_spmm_bf(const float* __restrict__ xin,
                                                 const float* __restrict__ eps,
                                                 int layer) {
    const float* hin = (layer == 0) ? xin : g_bufA;

    int wid  = (blockIdx.x * blockDim.x + threadIdx.x) >> 5;
    int lane = threadIdx.x & 31;

    int g = wid >> 9;
    const uint2* hg2 = (const uint2*)g_bufH + (size_t)g * NN * 32;

    float e1 = 1.0f + __ldg(&eps[layer]);
    int base = wid * 32 + lane;

    float4 h0 = ((const float4*)hin)[base];
    float4 acc;
    acc.x = e1 * h0.x; acc.y = e1 * h0.y; acc.z = e1 * h0.z; acc.w = e1 * h0.w;
    float4 acc1; acc1.x = 0.f; acc1.y = 0.f; acc1.z = 0.f; acc1.w = 0.f;

    int e    = g_row_ptr[wid];
    int eend = g_row_ptr[wid + 1];

    for (; e + 4 <= eend; e += 4) {
        int o0 = g_edge_off[e + 0];
        int o1 = g_edge_off[e + 1];
        int o2 = g_edge_off[e + 2];
        int o3 = g_edge_off[e + 3];
        uint2 v0 = hg2[o0 + lane];
        uint2 v1 = hg2[o1 + lane];
        uint2 v2 = hg2[o2 + lane];
        uint2 v3 = hg2[o3 + lane];
        acc.x  += __uint_as_float(v0.x << 16);
        acc.y  += __uint_as_float(v0.x & 0xffff0000u);
        acc.z  += __uint_as_float(v0.y << 16);
        acc.w  += __uint_as_float(v0.y & 0xffff0000u);
        acc1.x += __uint_as_float(v1.x << 16);
        acc1.y += __uint_as_float(v1.x & 0xffff0000u);
        acc1.z += __uint_as_float(v1.y << 16);
        acc1.w += __uint_as_float(v1.y & 0xffff0000u);
        acc.x  += __uint_as_float(v2.x << 16);
        acc.y  += __uint_as_float(v2.x & 0xffff0000u);
        acc.z  += __uint_as_float(v2.y << 16);
        acc.w  += __uint_as_float(v2.y & 0xffff0000u);
        acc1.x += __uint_as_float(v3.x << 16);
        acc1.y += __uint_as_float(v3.x & 0xffff0000u);
        acc1.z += __uint_as_float(v3.y << 16);
        acc1.w += __uint_as_float(v3.y & 0xffff0000u);
    }
    for (; e < eend; e++) {
        uint2 v0 = hg2[g_edge_off[e] + lane];
        acc.x += __uint_as_float(v0.x << 16);
        acc.y += __uint_as_float(v0.x & 0xffff0000u);
        acc.z += __uint_as_float(v0.y << 16);
        acc.w += __uint_as_float(v0.y & 0xffff0000u);
    }
    acc.x += acc1.x; acc.y += acc1.y; acc.z += acc1.z; acc.w += acc1.w;

    // split to bf16 hi/lo planes (arithmetic identical to R11's passing run)
    __nv_bfloat162 hA = __float22bfloat162_rn(make_float2(acc.x, acc.y));
    __nv_bfloat162 hB = __float22bfloat162_rn(make_float2(acc.z, acc.w));
    float2 fA = __bfloat1622float2(hA);
    float2 fB = __bfloat1622float2(hB);
    __nv_bfloat162 lA = __float22bfloat162_rn(make_float2(acc.x - fA.x, acc.y - fA.y));
    __nv_bfloat162 lB = __float22bfloat162_rn(make_float2(acc.z - fB.x, acc.w - fB.y));
    uint2 hw, lw;
    hw.x = *(unsigned*)&hA; hw.y = *(unsigned*)&hB;
    lw.x = *(unsigned*)&lA; lw.y = *(unsigned*)&lB;
    ((uint2*)g_Uh)[base] = hw;
    ((uint2*)g_Ul)[base] = lw;
}

// ---------------------------------------------------------------- tensor-core GEMM + bias + relu
// h = relu(U @ W_l + b_l). 3-pass bf16 split, fp32 accum. 256 thr, 2x64-row tiles,
// warp grid 2x4 (32x32 warp tiles), ldmatrix.x4 everywhere. U staged by pure uint4
// copy of prebuilt planes; TILE 1 PREFETCHED INTO REGISTERS during tile 0's MMA.
// Writes h fp32 to g_bufA + (optionally) bf16 copy to g_bufH via smem bounce.

#define SW 136   // bf16 elems per smem row (272 B stride, ldmatrix conflict-free)
#define SMEM_GEMM ((64*SW + 64*SW + HH*SW + HH*SW) * 2 + HH * 4)

#define MMA_BF16(C, A0, A1, A2, A3, B0, B1)                                      \
    asm volatile("mma.sync.aligned.m16n8k16.row.col.f32.bf16.bf16.f32 "          \
                 "{%0,%1,%2,%3}, {%4,%5,%6,%7}, {%8,%9}, {%0,%1,%2,%3};"         \
                 : "+f"(C[0]), "+f"(C[1]), "+f"(C[2]), "+f"(C[3])                \
                 : "r"(A0), "r"(A1), "r"(A2), "r"(A3), "r"(B0), "r"(B1))

#define LDMX4(R, addr)                                                           \
    asm volatile("ldmatrix.sync.aligned.m8n8.x4.shared.b16 {%0,%1,%2,%3}, [%4];" \
                 : "=r"(R[0]), "=r"(R[1]), "=r"(R[2]), "=r"(R[3]) : "r"(addr))

__global__ void __launch_bounds__(256) k_gemm_tc(const float* __restrict__ b,
                                                 int layer, int writeBF) {
    extern __shared__ char smem[];
    __nv_bfloat16* sUh = (__nv_bfloat16*)smem;
    __nv_bfloat16* sUl = sUh + 64 * SW;
    __nv_bfloat16* sWh = sUl + 64 * SW;
    __nv_bfloat16* sWl = sWh + HH * SW;
    float*         sB  = (float*)(sWl + HH * SW);

    int tid = threadIdx.x;

    // ---- stage W hi/lo once (packed bf16 [n][k]) ----
    {
        const uint4* wh4 = (const uint4*)(g_Wth + layer * HH * 64);
        const uint4* wl4 = (const uint4*)(g_Wtl + layer * HH * 64);
#pragma unroll
        for (int k = 0; k < 8; k++) {
            int q = tid + k * 256;            // 2048 uint4
            int n = q >> 4, cw = (q & 15) * 4;
            *(uint4*)(sWh + n * SW + cw * 2) = wh4[q];
            *(uint4*)(sWl + n * SW + cw * 2) = wl4[q];
        }
    }
    // ---- stage U tile 0: pure uint4 copy of prebuilt planes ----
    {
        int rowBase0 = blockIdx.x * 128;
        const uint4* uh4 = (const uint4*)(g_Uh + (size_t)rowBase0 * 64);
        const uint4* ul4 = (const uint4*)(g_Ul + (size_t)rowBase0 * 64);
#pragma unroll
        for (int k = 0; k < 4; k++) {
            int q = tid + k * 256;            // 1024 uint4 per plane
            int r = q >> 4, c4 = q & 15;
            *(uint4*)((unsigned*)sUh + r * 68 + c4 * 4) = uh4[q];
            *(uint4*)((unsigned*)sUl + r * 68 + c4 * 4) = ul4[q];
        }
    }
    if (tid < HH) sB[tid] = b[layer * HH + tid];

    int warp = tid >> 5, lane = tid & 31;
    int wm = warp & 1, wn = warp >> 1;
    int rw = wm * 32, nw = wn * 32;

    // ldmatrix lane addressing
    int lb = lane >> 3, lr = lane & 7;
    int a_row = (lb & 1) * 8 + lr;
    int a_k   = (lb >> 1) * 8;
    int b_n   = (lb >> 1) * 8 + lr;
    int b_k   = (lb & 1) * 8;

    unsigned aH[2], aL[2], bH[2], bL[2];
#pragma unroll
    for (int mt = 0; mt < 2; mt++) {
        int row = rw + mt * 16 + a_row;
        aH[mt] = (unsigned)__cvta_generic_to_shared(sUh + row * SW + a_k);
        aL[mt] = (unsigned)__cvta_generic_to_shared(sUl + row * SW + a_k);
    }
#pragma unroll
    for (int jp = 0; jp < 2; jp++) {
        int n = nw + jp * 16 + b_n;
        bH[jp] = (unsigned)__cvta_generic_to_shared(sWh + n * SW + b_k);
        bL[jp] = (unsigned)__cvta_generic_to_shared(sWl + n * SW + b_k);
    }

    int g2 = lane >> 2, tg = lane & 3;
    unsigned* sUhU = (unsigned*)sUh;

    uint4 ph[4], pl[4];                        // tile-1 prefetch registers

#pragma unroll
    for (int tile = 0; tile < 2; tile++) {
        int rowBase = blockIdx.x * 128 + tile * 64;

        if (tile == 1) {
            __syncthreads();   // all tile-0 smem reads + bounce done
            // STS tile-1 planes from prefetch regs (loads resolved via scoreboard)
#pragma unroll
            for (int k = 0; k < 4; k++) {
                int q = tid + k * 256;
                int r = q >> 4, c4 = q & 15;
                *(uint4*)((unsigned*)sUh + r * 68 + c4 * 4) = ph[k];
                *(uint4*)((unsigned*)sUl + r * 68 + c4 * 4) = pl[k];
            }
        }
        __syncthreads();

        if (tile == 0) {
            // issue tile-1 prefetch LDGs now; consumed after tile-0 MMA
            int rowBase1 = blockIdx.x * 128 + 64;
            const uint4* uh4 = (const uint4*)(g_Uh + (size_t)rowBase1 * 64);
            const uint4* ul4 = (const uint4*)(g_Ul + (size_t)rowBase1 * 64);
#pragma unroll
            for (int k = 0; k < 4; k++) {
                ph[k] = uh4[tid + k * 256];
                pl[k] = ul4[tid + k * 256];
            }
        }

        float acc[2][4][4];
#pragma unroll
        for (int mt = 0; mt < 2; mt++)
#pragma unroll
            for (int j = 0; j < 4; j++)
#pragma unroll
                for (int q = 0; q < 4; q++) acc[mt][j][q] = 0.f;

#pragma unroll
        for (int ks = 0; ks < 8; ks++) {
            unsigned ko = (unsigned)ks * 32;  // 16 bf16 = 32 bytes
            unsigned Ah[2][4], Al[2][4];
            LDMX4(Ah[0], aH[0] + ko); LDMX4(Ah[1], aH[1] + ko);
            LDMX4(Al[0], aL[0] + ko); LDMX4(Al[1], aL[1] + ko);
#pragma unroll
            for (int jp = 0; jp < 2; jp++) {
                unsigned Bh[4], Bl[4];
                LDMX4(Bh, bH[jp] + ko);
                LDMX4(Bl, bL[jp] + ko);
#pragma unroll
                for (int mt = 0; mt < 2; mt++) {
#pragma unroll
                    for (int jj = 0; jj < 2; jj++) {
                        int j = jp * 2 + jj;
                        MMA_BF16(acc[mt][j], Ah[mt][0], Ah[mt][1], Ah[mt][2], Ah[mt][3],
                                 Bh[jj * 2], Bh[jj * 2 + 1]);
                        MMA_BF16(acc[mt][j], Al[mt][0], Al[mt][1], Al[mt][2], Al[mt][3],
                                 Bh[jj * 2], Bh[jj * 2 + 1]);
                        MMA_BF16(acc[mt][j], Ah[mt][0], Ah[mt][1], Ah[mt][2], Ah[mt][3],
                                 Bl[jj * 2], Bl[jj * 2 + 1]);
                    }
                }
            }
        }

        // ---- epilogue: bias + relu; fp32 to g_bufA; bf16 packs kept in regs ----
        unsigned pk[2][4][2];
#pragma unroll
        for (int mt = 0; mt < 2; mt++) {
            int rA = rowBase + rw + mt * 16 + g2;
            int rB = rA + 8;
#pragma unroll
            for (int j = 0; j < 4; j++) {
                int c = nw + j * 8 + 2 * tg;
                float b0 = sB[c], b1 = sB[c + 1];
                float2 oA, oB;
                oA.x = fmaxf(acc[mt][j][0] + b0, 0.f);
                oA.y = fmaxf(acc[mt][j][1] + b1, 0.f);
                oB.x = fmaxf(acc[mt][j][2] + b0, 0.f);
                oB.y = fmaxf(acc[mt][j][3] + b1, 0.f);
                *(float2*)(g_bufA + (size_t)rA * HH + c) = oA;
                *(float2*)(g_bufA + (size_t)rB * HH + c) = oB;
                __nv_bfloat162 pA = __float22bfloat162_rn(oA);
                __nv_bfloat162 pB = __float22bfloat162_rn(oB);
                pk[mt][j][0] = *(unsigned*)&pA;
                pk[mt][j][1] = *(unsigned*)&pB;
            }
        }

        if (writeBF) {
            __syncthreads();    // all ldmatrix reads of sUh done
#pragma unroll
            for (int mt = 0; mt < 2; mt++) {
                int rloc = rw + mt * 16 + g2;
#pragma unroll
                for (int j = 0; j < 4; j++) {
                    int ch = (nw >> 1) + j * 4 + tg;
                    sUhU[rloc * 68 + ch]       = pk[mt][j][0];
                    sUhU[(rloc + 8) * 68 + ch] = pk[mt][j][1];
                }
            }
            __syncthreads();
#pragma unroll
            for (int k = 0; k < 4; k++) {
                int q = tid + k * 256;        // 1024 uint4
                int r = q >> 4, c4 = q & 15;
                ((uint4*)g_bufH)[(size_t)(rowBase + r) * 16 + c4] =
                    *(uint4*)((unsigned*)sUh + r * 68 + c4 * 4);
            }
        }
    }
}

// ---------------------------------------------------------------- readout stage 1: partial node sums
__global__ void __launch_bounds__(128) k_sum() {
    const float* h = g_bufA;
    int g = blockIdx.x >> 3, p = blockIdx.x & 7;
    int t = threadIdx.x;
    const float* base = h + (size_t)g * NN * HH + p * 64 * HH + t;
    float s0 = 0.f, s1 = 0.f;
#pragma unroll 8
    for (int r = 0; r < 64; r += 2) {
        s0 += base[r * HH];
        s1 += base[(r + 1) * HH];
    }
    g_part[(g * 8 + p) * HH + t] = s0 + s1;
}

// ---------------------------------------------------------------- readout stage 2: FCs + softmax
__global__ void __launch_bounds__(128) k_fc(const float* __restrict__ fc1w,
                                            const float* __restrict__ fc1b,
                                            const float* __restrict__ fc2w,
                                            const float* __restrict__ fc2b,
                                            float* __restrict__ out) {
    __shared__ float hg[HH];
    __shared__ float a1[HH];
    __shared__ float z[CC];
    __shared__ float ez[CC];

    int g = blockIdx.x;
    int t = threadIdx.x;

    float s = 0.f;
#pragma unroll
    for (int p = 0; p < 8; p++) s += g_part[(g * 8 + p) * HH + t];
    hg[t] = s;
    __syncthreads();

    {
        float acc = fc1b[t];
        for (int k = 0; k < HH; k++) acc += hg[k] * __ldg(&fc1w[k * HH + t]);
        a1[t] = fmaxf(acc, 0.f);
    }
    __syncthreads();

    if (t < CC) {
        float acc = fc2b[t];
        for (int k = 0; k < HH; k++) acc += a1[k] * __ldg(&fc2w[k * CC + t]);
        z[t] = acc;
    }
    __syncthreads();

    if (t < CC) {
        float m = z[0];
#pragma unroll
        for (int j = 1; j < CC; j++) m = fmaxf(m, z[j]);
        ez[t] = expf(z[t] - m);
    }
    __syncthreads();

    if (t < CC) {
        float ssum = 0.f;
#pragma unroll
        for (int j = 0; j < CC; j++) ssum += ez[j];
        out[g * CC + t] = ez[t] / ssum;
    }
}

// ---------------------------------------------------------------- launch
extern "C" void kernel_launch(void* const* d_in, const int* in_sizes, int n_in,
                              void* d_out, int out_size) {
    const float* x    = (const float*)d_in[0];
    const float* eps  = (const float*)d_in[1];
    const float* W    = (const float*)d_in[2];
    const float* b    = (const float*)d_in[3];
    const float* fc1w = (const float*)d_in[4];
    const float* fc1b = (const float*)d_in[5];
    const float* fc2w = (const float*)d_in[6];
    const float* fc2b = (const float*)d_in[7];
    const int*   src  = (const int*)d_in[8];
    const int*   dst  = (const int*)d_in[9];
    float* out = (float*)d_out;

    cudaFuncSetAttribute(k_gemm_tc, cudaFuncAttributeMaxDynamicSharedMemorySize,
                         SMEM_GEMM);

    k_csr<<<GG, 512>>>(src, dst);
    k_prepw<<<(LL * HH * 64 + 255) / 256, 256>>>(W);
    k_prepx<<<NV * 32 / 256, 256>>>(x);

    for (int l = 0; l < LL; l++) {
        k_spmm_bf<<<NV / 8, 256>>>(x, eps, l);
        k_gemm_tc<<<NV / 128, 256, SMEM_GEMM>>>(b, l, (l < LL - 1) ? 1 : 0);
    }

    k_sum<<<GG * 8, 128>>>();
    k_fc<<<GG, 128>>>(fc1w, fc1b, fc2w, fc2b, out);
}

// round 16
// speedup vs baseline: 1.2213x; 1.0671x over previous
#include <cuda_runtime.h>
#include <cuda_bf16.h>
#include <math.h>

#define GG 128
#define NN 512
#define NV (GG*NN)          // 65536 nodes
#define HH 128              // hidden/feature dim
#define EE 2097152          // directed edges
#define EHALF 8192
#define EPG 16384           // directed edges per graph
#define LL 5
#define CC 10

// Scratch (device globals: allocation-free per harness rules)
__device__ unsigned g_bufH[NV * 64];        // 16 MB: h (or x) packed bf16x2 — SOLE h representation
__device__ unsigned g_Uh[NV * 64];          // 16 MB: U hi plane (bf16x2 k-pairs)
__device__ unsigned g_Ul[NV * 64];          // 16 MB: U lo plane
__device__ int      g_row_ptr[NV + 1];
__device__ int      g_edge_off[EE];         // local src index * 32 (uint2-row offsets)
__device__ unsigned g_Wth[LL * HH * 64];    // W^T hi, packed bf16 k-pairs [l][n][kw]
__device__ unsigned g_Wtl[LL * HH * 64];    // W^T lo
__device__ float    g_part[GG * 8 * HH];    // readout partials

// ---------------------------------------------------------------- fused CSR build (R14 verbatim)
__global__ void __launch_bounds__(512) k_csr(const int* __restrict__ src,
                                             const int* __restrict__ dst) {
    __shared__ int cnt[NN];
    __shared__ int pos[NN];
    int g = blockIdx.x, t = threadIdx.x;
    cnt[t] = 0;
    __syncthreads();

    int base1 = g * EHALF;
    int base2 = GG * EHALF + g * EHALF;
    for (int i = t; i < EHALF; i += 512) {
        atomicAdd(&cnt[dst[base1 + i] & (NN - 1)], 1);
        atomicAdd(&cnt[dst[base2 + i] & (NN - 1)], 1);
    }
    __syncthreads();

    int c = cnt[t];
    pos[t] = c;
    __syncthreads();
    for (int off = 1; off < NN; off <<= 1) {
        int v = (t >= off) ? pos[t - off] : 0;
        __syncthreads();
        pos[t] += v;
        __syncthreads();
    }
    int startLocal = pos[t] - c;
    g_row_ptr[g * NN + t] = g * EPG + startLocal;
    cnt[t] = startLocal;
    if (g == 0 && t == 0) g_row_ptr[NV] = EE;
    __syncthreads();

    int* eout = g_edge_off + g * EPG;
    for (int i = t; i < EHALF; i += 512) {
        int d = dst[base1 + i] & (NN - 1);
        int p = atomicAdd(&cnt[d], 1);
        eout[p] = (src[base1 + i] & (NN - 1)) * 32;
        d = dst[base2 + i] & (NN - 1);
        p = atomicAdd(&cnt[d], 1);
        eout[p] = (src[base2 + i] & (NN - 1)) * 32;
    }
}

// ---------------------------------------------------------------- W prep: transpose + bf16 hi/lo split
__global__ void k_prepw(const float* __restrict__ W) {
    int i = blockIdx.x * blockDim.x + threadIdx.x;
    if (i >= LL * HH * 64) return;
    int kw = i & 63;
    int n  = (i >> 6) & (HH - 1);
    int l  = i >> 13;
    const float* Wl = W + l * HH * HH;
    float w0 = Wl[(2 * kw) * HH + n];
    float w1 = Wl[(2 * kw + 1) * HH + n];
    __nv_bfloat162 h = __float22bfloat162_rn(make_float2(w0, w1));
    float2 hf = __bfloat1622float2(h);
    __nv_bfloat162 lo = __float22bfloat162_rn(make_float2(w0 - hf.x, w1 - hf.y));
    g_Wth[i] = *reinterpret_cast<unsigned*>(&h);
    g_Wtl[i] = *reinterpret_cast<unsigned*>(&lo);
}

// ---------------------------------------------------------------- x -> bf16 gather copy
__global__ void __launch_bounds__(256) k_prepx(const float* __restrict__ x) {
    int i = blockIdx.x * 256 + threadIdx.x;
    float4 v = ((const float4*)x)[i];
    __nv_bfloat162 a = __float22bfloat162_rn(make_float2(v.x, v.y));
    __nv_bfloat162 b = __float22bfloat162_rn(make_float2(v.z, v.w));
    uint2 w;
    w.x = *(unsigned*)&a; w.y = *(unsigned*)&b;
    ((uint2*)g_bufH)[i] = w;
}

// ---------------------------------------------------------------- SpMM (bf16 gather + bf16 self-term)
// One warp per node; lane owns 4 feats (one uint2). All terms gathered bf16,
// converted by exact 16-bit shift, fp32 accumulation. Output: U hi/lo planes.
__global__ void __launch_bounds__(256) k_spmm_bf(const float* __restrict__ eps,
                                                 int layer) {
    int wid  = (blockIdx.x * blockDim.x + threadIdx.x) >> 5;
    int lane = threadIdx.x & 31;

    int g = wid >> 9;
    const uint2* hg2 = (const uint2*)g_bufH + (size_t)g * NN * 32;

    float e1 = 1.0f + __ldg(&eps[layer]);
    int base = wid * 32 + lane;

    uint2 sv = ((const uint2*)g_bufH)[base];
    float4 acc;
    acc.x = e1 * __uint_as_float(sv.x << 16);
    acc.y = e1 * __uint_as_float(sv.x & 0xffff0000u);
    acc.z = e1 * __uint_as_float(sv.y << 16);
    acc.w = e1 * __uint_as_float(sv.y & 0xffff0000u);
    float4 acc1; acc1.x = 0.f; acc1.y = 0.f; acc1.z = 0.f; acc1.w = 0.f;

    int e    = g_row_ptr[wid];
    int eend = g_row_ptr[wid + 1];

    for (; e + 4 <= eend; e += 4) {
        int o0 = g_edge_off[e + 0];
        int o1 = g_edge_off[e + 1];
        int o2 = g_edge_off[e + 2];
        int o3 = g_edge_off[e + 3];
        uint2 v0 = hg2[o0 + lane];
        uint2 v1 = hg2[o1 + lane];
        uint2 v2 = hg2[o2 + lane];
        uint2 v3 = hg2[o3 + lane];
        acc.x  += __uint_as_float(v0.x << 16);
        acc.y  += __uint_as_float(v0.x & 0xffff0000u);
        acc.z  += __uint_as_float(v0.y << 16);
        acc.w  += __uint_as_float(v0.y & 0xffff0000u);
        acc1.x += __uint_as_float(v1.x << 16);
        acc1.y += __uint_as_float(v1.x & 0xffff0000u);
        acc1.z += __uint_as_float(v1.y << 16);
        acc1.w += __uint_as_float(v1.y & 0xffff0000u);
        acc.x  += __uint_as_float(v2.x << 16);
        acc.y  += __uint_as_float(v2.x & 0xffff0000u);
        acc.z  += __uint_as_float(v2.y << 16);
        acc.w  += __uint_as_float(v2.y & 0xffff0000u);
        acc1.x += __uint_as_float(v3.x << 16);
        acc1.y += __uint_as_float(v3.x & 0xffff0000u);
        acc1.z += __uint_as_float(v3.y << 16);
        acc1.w += __uint_as_float(v3.y & 0xffff0000u);
    }
    for (; e < eend; e++) {
        uint2 v0 = hg2[g_edge_off[e] + lane];
        acc.x += __uint_as_float(v0.x << 16);
        acc.y += __uint_as_float(v0.x & 0xffff0000u);
        acc.z += __uint_as_float(v0.y << 16);
        acc.w += __uint_as_float(v0.y & 0xffff0000u);
    }
    acc.x += acc1.x; acc.y += acc1.y; acc.z += acc1.z; acc.w += acc1.w;

    // split to bf16 hi/lo planes (exact split of fp32 acc)
    __nv_bfloat162 hA = __float22bfloat162_rn(make_float2(acc.x, acc.y));
    __nv_bfloat162 hB = __float22bfloat162_rn(make_float2(acc.z, acc.w));
    float2 fA = __bfloat1622float2(hA);
    float2 fB = __bfloat1622float2(hB);
    __nv_bfloat162 lA = __float22bfloat162_rn(make_float2(acc.x - fA.x, acc.y - fA.y));
    __nv_bfloat162 lB = __float22bfloat162_rn(make_float2(acc.z - fB.x, acc.w - fB.y));
    uint2 hw, lw;
    hw.x = *(unsigned*)&hA; hw.y = *(unsigned*)&hB;
    lw.x = *(unsigned*)&lA; lw.y = *(unsigned*)&lB;
    ((uint2*)g_Uh)[base] = hw;
    ((uint2*)g_Ul)[base] = lw;
}

// ---------------------------------------------------------------- tensor-core GEMM + bias + relu
// h = relu(U @ W_l + b_l). 3-pass bf16 split, fp32 accum. 256 thr, 2x64-row tiles,
// warp grid 2x4 (32x32 warp tiles), ldmatrix.x4. U staged by pure uint4 copy;
// tile 1 register-prefetched during tile 0's MMA. Output: bf16 h ONLY, via
// conflict-free smem bounce + coalesced uint4 store (no scattered fp32 writes).

#define SW 136   // bf16 elems per smem row (272 B stride, ldmatrix conflict-free)
#define SMEM_GEMM ((64*SW + 64*SW + HH*SW + HH*SW) * 2 + HH * 4)

#define MMA_BF16(C, A0, A1, A2, A3, B0, B1)                                      \
    asm volatile("mma.sync.aligned.m16n8k16.row.col.f32.bf16.bf16.f32 "          \
                 "{%0,%1,%2,%3}, {%4,%5,%6,%7}, {%8,%9}, {%0,%1,%2,%3};"         \
                 : "+f"(C[0]), "+f"(C[1]), "+f"(C[2]), "+f"(C[3])                \
                 : "r"(A0), "r"(A1), "r"(A2), "r"(A3), "r"(B0), "r"(B1))

#define LDMX4(R, addr)                                                           \
    asm volatile("ldmatrix.sync.aligned.m8n8.x4.shared.b16 {%0,%1,%2,%3}, [%4];" \
                 : "=r"(R[0]), "=r"(R[1]), "=r"(R[2]), "=r"(R[3]) : "r"(addr))

__global__ void __launch_bounds__(256) k_gemm_tc(const float* __restrict__ b,
                                                 int layer) {
    extern __shared__ char smem[];
    __nv_bfloat16* sUh = (__nv_bfloat16*)smem;
    __nv_bfloat16* sUl = sUh + 64 * SW;
    __nv_bfloat16* sWh = sUl + 64 * SW;
    __nv_bfloat16* sWl = sWh + HH * SW;
    float*         sB  = (float*)(sWl + HH * SW);

    int tid = threadIdx.x;

    // ---- stage W hi/lo once (packed bf16 [n][k]) ----
    {
        const uint4* wh4 = (const uint4*)(g_Wth + layer * HH * 64);
        const uint4* wl4 = (const uint4*)(g_Wtl + layer * HH * 64);
#pragma unroll
        for (int k = 0; k < 8; k++) {
            int q = tid + k * 256;            // 2048 uint4
            int n = q >> 4, cw = (q & 15) * 4;
            *(uint4*)(sWh + n * SW + cw * 2) = wh4[q];
            *(uint4*)(sWl + n * SW + cw * 2) = wl4[q];
        }
    }
    // ---- stage U tile 0: pure uint4 copy of prebuilt planes ----
    {
        int rowBase0 = blockIdx.x * 128;
        const uint4* uh4 = (const uint4*)(g_Uh + (size_t)rowBase0 * 64);
        const uint4* ul4 = (const uint4*)(g_Ul + (size_t)rowBase0 * 64);
#pragma unroll
        for (int k = 0; k < 4; k++) {
            int q = tid + k * 256;            // 1024 uint4 per plane
            int r = q >> 4, c4 = q & 15;
            *(uint4*)((unsigned*)sUh + r * 68 + c4 * 4) = uh4[q];
            *(uint4*)((unsigned*)sUl + r * 68 + c4 * 4) = ul4[q];
        }
    }
    if (tid < HH) sB[tid] = b[layer * HH + tid];

    int warp = tid >> 5, lane = tid & 31;
    int wm = warp & 1, wn = warp >> 1;
    int rw = wm * 32, nw = wn * 32;

    // ldmatrix lane addressing
    int lb = lane >> 3, lr = lane & 7;
    int a_row = (lb & 1) * 8 + lr;
    int a_k   = (lb >> 1) * 8;
    int b_n   = (lb >> 1) * 8 + lr;
    int b_k   = (lb & 1) * 8;

    unsigned aH[2], aL[2], bH[2], bL[2];
#pragma unroll
    for (int mt = 0; mt < 2; mt++) {
        int row = rw + mt * 16 + a_row;
        aH[mt] = (unsigned)__cvta_generic_to_shared(sUh + row * SW + a_k);
        aL[mt] = (unsigned)__cvta_generic_to_shared(sUl + row * SW + a_k);
    }
#pragma unroll
    for (int jp = 0; jp < 2; jp++) {
        int n = nw + jp * 16 + b_n;
        bH[jp] = (unsigned)__cvta_generic_to_shared(sWh + n * SW + b_k);
        bL[jp] = (unsigned)__cvta_generic_to_shared(sWl + n * SW + b_k);
    }

    int g2 = lane >> 2, tg = lane & 3;
    unsigned* sUhU = (unsigned*)sUh;

    uint4 ph[4], pl[4];                        // tile-1 prefetch registers

#pragma unroll
    for (int tile = 0; tile < 2; tile++) {
        int rowBase = blockIdx.x * 128 + tile * 64;

        if (tile == 1) {
            __syncthreads();   // all tile-0 smem reads + bounce done
#pragma unroll
            for (int k = 0; k < 4; k++) {
                int q = tid + k * 256;
                int r = q >> 4, c4 = q & 15;
                *(uint4*)((unsigned*)sUh + r * 68 + c4 * 4) = ph[k];
                *(uint4*)((unsigned*)sUl + r * 68 + c4 * 4) = pl[k];
            }
        }
        __syncthreads();

        if (tile == 0) {
            // issue tile-1 prefetch LDGs now; consumed after tile-0 MMA
            int rowBase1 = blockIdx.x * 128 + 64;
            const uint4* uh4 = (const uint4*)(g_Uh + (size_t)rowBase1 * 64);
            const uint4* ul4 = (const uint4*)(g_Ul + (size_t)rowBase1 * 64);
#pragma unroll
            for (int k = 0; k < 4; k++) {
                ph[k] = uh4[tid + k * 256];
                pl[k] = ul4[tid + k * 256];
            }
        }

        float acc[2][4][4];
#pragma unroll
        for (int mt = 0; mt < 2; mt++)
#pragma unroll
            for (int j = 0; j < 4; j++)
#pragma unroll
                for (int q = 0; q < 4; q++) acc[mt][j][q] = 0.f;

#pragma unroll
        for (int ks = 0; ks < 8; ks++) {
            unsigned ko = (unsigned)ks * 32;  // 16 bf16 = 32 bytes
            unsigned Ah[2][4], Al[2][4];
            LDMX4(Ah[0], aH[0] + ko); LDMX4(Ah[1], aH[1] + ko);
            LDMX4(Al[0], aL[0] + ko); LDMX4(Al[1], aL[1] + ko);
#pragma unroll
            for (int jp = 0; jp < 2; jp++) {
                unsigned Bh[4], Bl[4];
                LDMX4(Bh, bH[jp] + ko);
                LDMX4(Bl, bL[jp] + ko);
#pragma unroll
                for (int mt = 0; mt < 2; mt++) {
#pragma unroll
                    for (int jj = 0; jj < 2; jj++) {
                        int j = jp * 2 + jj;
                        MMA_BF16(acc[mt][j], Ah[mt][0], Ah[mt][1], Ah[mt][2], Ah[mt][3],
                                 Bh[jj * 2], Bh[jj * 2 + 1]);
                        MMA_BF16(acc[mt][j], Al[mt][0], Al[mt][1], Al[mt][2], Al[mt][3],
                                 Bh[jj * 2], Bh[jj * 2 + 1]);
                        MMA_BF16(acc[mt][j], Ah[mt][0], Ah[mt][1], Ah[mt][2], Ah[mt][3],
                                 Bl[jj * 2], Bl[jj * 2 + 1]);
                    }
                }
            }
        }

        // ---- epilogue: bias + relu -> bf16 packs (registers only) ----
        unsigned pk[2][4][2];
#pragma unroll
        for (int mt = 0; mt < 2; mt++) {
#pragma unroll
            for (int j = 0; j < 4; j++) {
                int c = nw + j * 8 + 2 * tg;
                float b0 = sB[c], b1 = sB[c + 1];
                float2 oA, oB;
                oA.x = fmaxf(acc[mt][j][0] + b0, 0.f);
                oA.y = fmaxf(acc[mt][j][1] + b1, 0.f);
                oB.x = fmaxf(acc[mt][j][2] + b0, 0.f);
                oB.y = fmaxf(acc[mt][j][3] + b1, 0.f);
                __nv_bfloat162 pA = __float22bfloat162_rn(oA);
                __nv_bfloat162 pB = __float22bfloat162_rn(oB);
                pk[mt][j][0] = *(unsigned*)&pA;
                pk[mt][j][1] = *(unsigned*)&pB;
            }
        }

        __syncthreads();    // all ldmatrix reads of sUh done
#pragma unroll
        for (int mt = 0; mt < 2; mt++) {
            int rloc = rw + mt * 16 + g2;
#pragma unroll
            for (int j = 0; j < 4; j++) {
                int ch = (nw >> 1) + j * 4 + tg;
                sUhU[rloc * 68 + ch]       = pk[mt][j][0];
                sUhU[(rloc + 8) * 68 + ch] = pk[mt][j][1];
            }
        }
        __syncthreads();
#pragma unroll
        for (int k = 0; k < 4; k++) {
            int q = tid + k * 256;            // 1024 uint4
            int r = q >> 4, c4 = q & 15;
            ((uint4*)g_bufH)[(size_t)(rowBase + r) * 16 + c4] =
                *(uint4*)((unsigned*)sUh + r * 68 + c4 * 4);
        }
    }
}

// ---------------------------------------------------------------- readout stage 1: partial node sums (bf16 in)
__global__ void __launch_bounds__(64) k_sum() {
    int g = blockIdx.x >> 3, p = blockIdx.x & 7;
    int t = threadIdx.x;                       // 0..63: uint column
    const unsigned* base = g_bufH + (size_t)g * NN * 64 + p * 64 * 64 + t;
    float lo0 = 0.f, hi0 = 0.f, lo1 = 0.f, hi1 = 0.f;
#pragma unroll 8
    for (int r = 0; r < 64; r += 2) {
        unsigned u0 = base[r * 64];
        unsigned u1 = base[(r + 1) * 64];
        lo0 += __uint_as_float(u0 << 16);
        hi0 += __uint_as_float(u0 & 0xffff0000u);
        lo1 += __uint_as_float(u1 << 16);
        hi1 += __uint_as_float(u1 & 0xffff0000u);
    }
    g_part[(g * 8 + p) * HH + 2 * t]     = lo0 + lo1;
    g_part[(g * 8 + p) * HH + 2 * t + 1] = hi0 + hi1;
}

// ---------------------------------------------------------------- readout stage 2: FCs + softmax
__global__ void __launch_bounds__(128) k_fc(const float* __restrict__ fc1w,
                                            const float* __restrict__ fc1b,
                                            const float* __restrict__ fc2w,
                                            const float* __restrict__ fc2b,
                                            float* __restrict__ out) {
    __shared__ float hg[HH];
    __shared__ float a1[HH];
    __shared__ float z[CC];
    __shared__ float ez[CC];

    int g = blockIdx.x;
    int t = threadIdx.x;

    float s = 0.f;
#pragma unroll
    for (int p = 0; p < 8; p++) s += g_part[(g * 8 + p) * HH + t];
    hg[t] = s;
    __syncthreads();

    {
        float acc = fc1b[t];
        for (int k = 0; k < HH; k++) acc += hg[k] * __ldg(&fc1w[k * HH + t]);
        a1[t] = fmaxf(acc, 0.f);
    }
    __syncthreads();

    if (t < CC) {
        float acc = fc2b[t];
        for (int k = 0; k < HH; k++) acc += a1[k] * __ldg(&fc2w[k * CC + t]);
        z[t] = acc;
    }
    __syncthreads();

    if (t < CC) {
        float m = z[0];
#pragma unroll
        for (int j = 1; j < CC; j++) m = fmaxf(m, z[j]);
        ez[t] = expf(z[t] - m);
    }
    __syncthreads();

    if (t < CC) {
        float ssum = 0.f;
#pragma unroll
        for (int j = 0; j < CC; j++) ssum += ez[j];
        out[g * CC + t] = ez[t] / ssum;
    }
}

// ---------------------------------------------------------------- launch
extern "C" void kernel_launch(void* const* d_in, const int* in_sizes, int n_in,
                              void* d_out, int out_size) {
    const float* x    = (const float*)d_in[0];
    const float* eps  = (const float*)d_in[1];
    const float* W    = (const float*)d_in[2];
    const float* b    = (const float*)d_in[3];
    const float* fc1w = (const float*)d_in[4];
    const float* fc1b = (const float*)d_in[5];
    const float* fc2w = (const float*)d_in[6];
    const float* fc2b = (const float*)d_in[7];
    const int*   src  = (const int*)d_in[8];
    const int*   dst  = (const int*)d_in[9];
    float* out = (float*)d_out;

    cudaFuncSetAttribute(k_gemm_tc, cudaFuncAttributeMaxDynamicSharedMemorySize,
                         SMEM_GEMM);

    k_csr<<<GG, 512>>>(src, dst);
    k_prepw<<<(LL * HH * 64 + 255) / 256, 256>>>(W);
    k_prepx<<<NV * 32 / 256, 256>>>(x);

    for (int l = 0; l < LL; l++) {
        k_spmm_bf<<<NV / 8, 256>>>(eps, l);
        k_gemm_tc<<<NV / 128, 256, SMEM_GEMM>>>(b, l);
    }

    k_sum<<<GG * 8, 64>>>();
    k_fc<<<GG, 128>>>(fc1w, fc1b, fc2w, fc2b, out);
}

// round 17
// speedup vs baseline: 1.4852x; 1.2161x over previous
#include <cuda_runtime.h>
#include <cuda_bf16.h>
#include <math.h>

#define GG 128
#define NN 512
#define NV (GG*NN)          // 65536 nodes
#define HH 128              // hidden/feature dim
#define EE 2097152          // directed edges
#define EHALF 8192
#define EPG 16384           // directed edges per graph
#define LL 5
#define CC 10

// Scratch (device globals: allocation-free per harness rules)
__device__ unsigned g_bufH[NV * 64];        // 16 MB: h (or x) packed bf16x2 — sole h representation
__device__ unsigned g_U[NV * 64];           // 16 MB: U packed bf16x2 k-pairs (SpMM out, GEMM in)
__device__ int      g_row_ptr[NV + 1];
__device__ int      g_edge_off[EE];         // local src index * 32 (uint2-row offsets)
__device__ unsigned g_Wt[LL * HH * 64];     // W^T packed bf16 k-pairs [l][n][kw]
__device__ float    g_part[GG * 8 * HH];    // readout partials

// ---------------------------------------------------------------- fused CSR build (verbatim)
__global__ void __launch_bounds__(512) k_csr(const int* __restrict__ src,
                                             const int* __restrict__ dst) {
    __shared__ int cnt[NN];
    __shared__ int pos[NN];
    int g = blockIdx.x, t = threadIdx.x;
    cnt[t] = 0;
    __syncthreads();

    int base1 = g * EHALF;
    int base2 = GG * EHALF + g * EHALF;
    for (int i = t; i < EHALF; i += 512) {
        atomicAdd(&cnt[dst[base1 + i] & (NN - 1)], 1);
        atomicAdd(&cnt[dst[base2 + i] & (NN - 1)], 1);
    }
    __syncthreads();

    int c = cnt[t];
    pos[t] = c;
    __syncthreads();
    for (int off = 1; off < NN; off <<= 1) {
        int v = (t >= off) ? pos[t - off] : 0;
        __syncthreads();
        pos[t] += v;
        __syncthreads();
    }
    int startLocal = pos[t] - c;
    g_row_ptr[g * NN + t] = g * EPG + startLocal;
    cnt[t] = startLocal;
    if (g == 0 && t == 0) g_row_ptr[NV] = EE;
    __syncthreads();

    int* eout = g_edge_off + g * EPG;
    for (int i = t; i < EHALF; i += 512) {
        int d = dst[base1 + i] & (NN - 1);
        int p = atomicAdd(&cnt[d], 1);
        eout[p] = (src[base1 + i] & (NN - 1)) * 32;
        d = dst[base2 + i] & (NN - 1);
        p = atomicAdd(&cnt[d], 1);
        eout[p] = (src[base2 + i] & (NN - 1)) * 32;
    }
}

// ---------------------------------------------------------------- W prep: transpose + bf16 round
__global__ void k_prepw(const float* __restrict__ W) {
    int i = blockIdx.x * blockDim.x + threadIdx.x;
    if (i >= LL * HH * 64) return;
    int kw = i & 63;
    int n  = (i >> 6) & (HH - 1);
    int l  = i >> 13;
    const float* Wl = W + l * HH * HH;
    float w0 = Wl[(2 * kw) * HH + n];
    float w1 = Wl[(2 * kw + 1) * HH + n];
    __nv_bfloat162 h = __float22bfloat162_rn(make_float2(w0, w1));
    g_Wt[i] = *reinterpret_cast<unsigned*>(&h);
}

// ---------------------------------------------------------------- x -> bf16 gather copy
__global__ void __launch_bounds__(256) k_prepx(const float* __restrict__ x) {
    int i = blockIdx.x * 256 + threadIdx.x;
    float4 v = ((const float4*)x)[i];
    __nv_bfloat162 a = __float22bfloat162_rn(make_float2(v.x, v.y));
    __nv_bfloat162 b = __float22bfloat162_rn(make_float2(v.z, v.w));
    uint2 w;
    w.x = *(unsigned*)&a; w.y = *(unsigned*)&b;
    ((uint2*)g_bufH)[i] = w;
}

// ---------------------------------------------------------------- SpMM (bf16 gather, fp32 accum)
// One warp per node; lane owns 4 feats (one uint2). All terms gathered bf16,
// converted by exact 16-bit shift, fp32 accumulation. Output: U bf16 packed.
__global__ void __launch_bounds__(256) k_spmm_bf(const float* __restrict__ eps,
                                                 int layer) {
    int wid  = (blockIdx.x * blockDim.x + threadIdx.x) >> 5;
    int lane = threadIdx.x & 31;

    int g = wid >> 9;
    const uint2* hg2 = (const uint2*)g_bufH + (size_t)g * NN * 32;

    float e1 = 1.0f + __ldg(&eps[layer]);
    int base = wid * 32 + lane;

    uint2 sv = ((const uint2*)g_bufH)[base];
    float4 acc;
    acc.x = e1 * __uint_as_float(sv.x << 16);
    acc.y = e1 * __uint_as_float(sv.x & 0xffff0000u);
    acc.z = e1 * __uint_as_float(sv.y << 16);
    acc.w = e1 * __uint_as_float(sv.y & 0xffff0000u);
    float4 acc1; acc1.x = 0.f; acc1.y = 0.f; acc1.z = 0.f; acc1.w = 0.f;

    int e    = g_row_ptr[wid];
    int eend = g_row_ptr[wid + 1];

    for (; e + 4 <= eend; e += 4) {
        int o0 = g_edge_off[e + 0];
        int o1 = g_edge_off[e + 1];
        int o2 = g_edge_off[e + 2];
        int o3 = g_edge_off[e + 3];
        uint2 v0 = hg2[o0 + lane];
        uint2 v1 = hg2[o1 + lane];
        uint2 v2 = hg2[o2 + lane];
        uint2 v3 = hg2[o3 + lane];
        acc.x  += __uint_as_float(v0.x << 16);
        acc.y  += __uint_as_float(v0.x & 0xffff0000u);
        acc.z  += __uint_as_float(v0.y << 16);
        acc.w  += __uint_as_float(v0.y & 0xffff0000u);
        acc1.x += __uint_as_float(v1.x << 16);
        acc1.y += __uint_as_float(v1.x & 0xffff0000u);
        acc1.z += __uint_as_float(v1.y << 16);
        acc1.w += __uint_as_float(v1.y & 0xffff0000u);
        acc.x  += __uint_as_float(v2.x << 16);
        acc.y  += __uint_as_float(v2.x & 0xffff0000u);
        acc.z  += __uint_as_float(v2.y << 16);
        acc.w  += __uint_as_float(v2.y & 0xffff0000u);
        acc1.x += __uint_as_float(v3.x << 16);
        acc1.y += __uint_as_float(v3.x & 0xffff0000u);
        acc1.z += __uint_as_float(v3.y << 16);
        acc1.w += __uint_as_float(v3.y & 0xffff0000u);
    }
    for (; e < eend; e++) {
        uint2 v0 = hg2[g_edge_off[e] + lane];
        acc.x += __uint_as_float(v0.x << 16);
        acc.y += __uint_as_float(v0.x & 0xffff0000u);
        acc.z += __uint_as_float(v0.y << 16);
        acc.w += __uint_as_float(v0.y & 0xffff0000u);
    }
    acc.x += acc1.x; acc.y += acc1.y; acc.z += acc1.z; acc.w += acc1.w;

    __nv_bfloat162 hA = __float22bfloat162_rn(make_float2(acc.x, acc.y));
    __nv_bfloat162 hB = __float22bfloat162_rn(make_float2(acc.z, acc.w));
    uint2 hw;
    hw.x = *(unsigned*)&hA; hw.y = *(unsigned*)&hB;
    ((uint2*)g_U)[base] = hw;
}

// ---------------------------------------------------------------- tensor-core GEMM + bias + relu
// h = relu(U @ W_l + b_l). SINGLE-PASS pure bf16, fp32 accum. 256 thr,
// 2x64-row tiles, warp grid 2x4 (32x32 warp tiles), ldmatrix.x4. U staged by
// pure uint4 copy; tile 1 register-prefetched during tile 0's MMA.
// Output: bf16 h via conflict-free smem bounce + coalesced uint4 store.

#define SW 136   // bf16 elems per smem row (272 B stride, ldmatrix conflict-free)
#define SMEM_GEMM (64*SW*2 + HH*SW*2 + HH*4)   // 17408 + 34816 + 512 = 52736 B

#define MMA_BF16(C, A0, A1, A2, A3, B0, B1)                                      \
    asm volatile("mma.sync.aligned.m16n8k16.row.col.f32.bf16.bf16.f32 "          \
                 "{%0,%1,%2,%3}, {%4,%5,%6,%7}, {%8,%9}, {%0,%1,%2,%3};"         \
                 : "+f"(C[0]), "+f"(C[1]), "+f"(C[2]), "+f"(C[3])                \
                 : "r"(A0), "r"(A1), "r"(A2), "r"(A3), "r"(B0), "r"(B1))

#define LDMX4(R, addr)                                                           \
    asm volatile("ldmatrix.sync.aligned.m8n8.x4.shared.b16 {%0,%1,%2,%3}, [%4];" \
                 : "=r"(R[0]), "=r"(R[1]), "=r"(R[2]), "=r"(R[3]) : "r"(addr))

__global__ void __launch_bounds__(256) k_gemm_tc(const float* __restrict__ b,
                                                 int layer) {
    extern __shared__ char smem[];
    __nv_bfloat16* sU = (__nv_bfloat16*)smem;
    __nv_bfloat16* sW = sU + 64 * SW;
    float*         sB = (float*)(sW + HH * SW);

    int tid = threadIdx.x;

    // ---- stage W once (packed bf16 [n][k]) ----
    {
        const uint4* w4 = (const uint4*)(g_Wt + layer * HH * 64);
#pragma unroll
        for (int k = 0; k < 8; k++) {
            int q = tid + k * 256;            // 2048 uint4
            int n = q >> 4, cw = (q & 15) * 4;
            *(uint4*)(sW + n * SW + cw * 2) = w4[q];
        }
    }
    // ---- stage U tile 0: pure uint4 copy ----
    {
        int rowBase0 = blockIdx.x * 128;
        const uint4* u4 = (const uint4*)(g_U + (size_t)rowBase0 * 64);
#pragma unroll
        for (int k = 0; k < 4; k++) {
            int q = tid + k * 256;            // 1024 uint4
            int r = q >> 4, c4 = q & 15;
            *(uint4*)((unsigned*)sU + r * 68 + c4 * 4) = u4[q];
        }
    }
    if (tid < HH) sB[tid] = b[layer * HH + tid];

    int warp = tid >> 5, lane = tid & 31;
    int wm = warp & 1, wn = warp >> 1;
    int rw = wm * 32, nw = wn * 32;

    // ldmatrix lane addressing
    int lb = lane >> 3, lr = lane & 7;
    int a_row = (lb & 1) * 8 + lr;
    int a_k   = (lb >> 1) * 8;
    int b_n   = (lb >> 1) * 8 + lr;
    int b_k   = (lb & 1) * 8;

    unsigned aA[2], bB[2];
#pragma unroll
    for (int mt = 0; mt < 2; mt++) {
        int row = rw + mt * 16 + a_row;
        aA[mt] = (unsigned)__cvta_generic_to_shared(sU + row * SW + a_k);
    }
#pragma unroll
    for (int jp = 0; jp < 2; jp++) {
        int n = nw + jp * 16 + b_n;
        bB[jp] = (unsigned)__cvta_generic_to_shared(sW + n * SW + b_k);
    }

    int g2 = lane >> 2, tg = lane & 3;
    unsigned* sUU = (unsigned*)sU;

    uint4 ph[4];                               // tile-1 prefetch registers

#pragma unroll
    for (int tile = 0; tile < 2; tile++) {
        int rowBase = blockIdx.x * 128 + tile * 64;

        if (tile == 1) {
            __syncthreads();   // all tile-0 smem reads + bounce done
#pragma unroll
            for (int k = 0; k < 4; k++) {
                int q = tid + k * 256;
                int r = q >> 4, c4 = q & 15;
                *(uint4*)((unsigned*)sU + r * 68 + c4 * 4) = ph[k];
            }
        }
        __syncthreads();

        if (tile == 0) {
            int rowBase1 = blockIdx.x * 128 + 64;
            const uint4* u4 = (const uint4*)(g_U + (size_t)rowBase1 * 64);
#pragma unroll
            for (int k = 0; k < 4; k++) ph[k] = u4[tid + k * 256];
        }

        float acc[2][4][4];
#pragma unroll
        for (int mt = 0; mt < 2; mt++)
#pragma unroll
            for (int j = 0; j < 4; j++)
#pragma unroll
                for (int q = 0; q < 4; q++) acc[mt][j][q] = 0.f;

#pragma unroll
        for (int ks = 0; ks < 8; ks++) {
            unsigned ko = (unsigned)ks * 32;  // 16 bf16 = 32 bytes
            unsigned Ah[2][4];
            LDMX4(Ah[0], aA[0] + ko); LDMX4(Ah[1], aA[1] + ko);
#pragma unroll
            for (int jp = 0; jp < 2; jp++) {
                unsigned Bh[4];
                LDMX4(Bh, bB[jp] + ko);
#pragma unroll
                for (int mt = 0; mt < 2; mt++) {
#pragma unroll
                    for (int jj = 0; jj < 2; jj++) {
                        int j = jp * 2 + jj;
                        MMA_BF16(acc[mt][j], Ah[mt][0], Ah[mt][1], Ah[mt][2], Ah[mt][3],
                                 Bh[jj * 2], Bh[jj * 2 + 1]);
                    }
                }
            }
        }

        // ---- epilogue: bias + relu -> bf16 packs (registers only) ----
        unsigned pk[2][4][2];
#pragma unroll
        for (int mt = 0; mt < 2; mt++) {
#pragma unroll
            for (int j = 0; j < 4; j++) {
                int c = nw + j * 8 + 2 * tg;
                float b0 = sB[c], b1 = sB[c + 1];
                float2 oA, oB;
                oA.x = fmaxf(acc[mt][j][0] + b0, 0.f);
                oA.y = fmaxf(acc[mt][j][1] + b1, 0.f);
                oB.x = fmaxf(acc[mt][j][2] + b0, 0.f);
                oB.y = fmaxf(acc[mt][j][3] + b1, 0.f);
                __nv_bfloat162 pA = __float22bfloat162_rn(oA);
                __nv_bfloat162 pB = __float22bfloat162_rn(oB);
                pk[mt][j][0] = *(unsigned*)&pA;
                pk[mt][j][1] = *(unsigned*)&pB;
            }
        }

        __syncthreads();    // all ldmatrix reads of sU done
#pragma unroll
        for (int mt = 0; mt < 2; mt++) {
            int rloc = rw + mt * 16 + g2;
#pragma unroll
            for (int j = 0; j < 4; j++) {
                int ch = (nw >> 1) + j * 4 + tg;
                sUU[rloc * 68 + ch]       = pk[mt][j][0];
                sUU[(rloc + 8) * 68 + ch] = pk[mt][j][1];
            }
        }
        __syncthreads();
#pragma unroll
        for (int k = 0; k < 4; k++) {
            int q = tid + k * 256;            // 1024 uint4
            int r = q >> 4, c4 = q & 15;
            ((uint4*)g_bufH)[(size_t)(rowBase + r) * 16 + c4] =
                *(uint4*)((unsigned*)sU + r * 68 + c4 * 4);
        }
    }
}

// ---------------------------------------------------------------- readout stage 1: partial node sums (bf16 in)
__global__ void __launch_bounds__(64) k_sum() {
    int g = blockIdx.x >> 3, p = blockIdx.x & 7;
    int t = threadIdx.x;                       // 0..63: uint column
    const unsigned* base = g_bufH + (size_t)g * NN * 64 + p * 64 * 64 + t;
    float lo0 = 0.f, hi0 = 0.f, lo1 = 0.f, hi1 = 0.f;
#pragma unroll 8
    for (int r = 0; r < 64; r += 2) {
        unsigned u0 = base[r * 64];
        unsigned u1 = base[(r + 1) * 64];
        lo0 += __uint_as_float(u0 << 16);
        hi0 += __uint_as_float(u0 & 0xffff0000u);
        lo1 += __uint_as_float(u1 << 16);
        hi1 += __uint_as_float(u1 & 0xffff0000u);
    }
    g_part[(g * 8 + p) * HH + 2 * t]     = lo0 + lo1;
    g_part[(g * 8 + p) * HH + 2 * t + 1] = hi0 + hi1;
}

// ---------------------------------------------------------------- readout stage 2: FCs + softmax
__global__ void __launch_bounds__(128) k_fc(const float* __restrict__ fc1w,
                                            const float* __restrict__ fc1b,
                                            const float* __restrict__ fc2w,
                                            const float* __restrict__ fc2b,
                                            float* __restrict__ out) {
    __shared__ float hg[HH];
    __shared__ float a1[HH];
    __shared__ float z[CC];
    __shared__ float ez[CC];

    int g = blockIdx.x;
    int t = threadIdx.x;

    float s = 0.f;
#pragma unroll
    for (int p = 0; p < 8; p++) s += g_part[(g * 8 + p) * HH + t];
    hg[t] = s;
    __syncthreads();

    {
        float acc = fc1b[t];
        for (int k = 0; k < HH; k++) acc += hg[k] * __ldg(&fc1w[k * HH + t]);
        a1[t] = fmaxf(acc, 0.f);
    }
    __syncthreads();

    if (t < CC) {
        float acc = fc2b[t];
        for (int k = 0; k < HH; k++) acc += a1[k] * __ldg(&fc2w[k * CC + t]);
        z[t] = acc;
    }
    __syncthreads();

    if (t < CC) {
        float m = z[0];
#pragma unroll
        for (int j = 1; j < CC; j++) m = fmaxf(m, z[j]);
        ez[t] = expf(z[t] - m);
    }
    __syncthreads();

    if (t < CC) {
        float ssum = 0.f;
#pragma unroll
        for (int j = 0; j < CC; j++) ssum += ez[j];
        out[g * CC + t] = ez[t] / ssum;
    }
}

// ---------------------------------------------------------------- launch
extern "C" void kernel_launch(void* const* d_in, const int* in_sizes, int n_in,
                              void* d_out, int out_size) {
    const float* x    = (const float*)d_in[0];
    const float* eps  = (const float*)d_in[1];
    const float* W    = (const float*)d_in[2];
    const float* b    = (const float*)d_in[3];
    const float* fc1w = (const float*)d_in[4];
    const float* fc1b = (const float*)d_in[5];
    const float* fc2w = (const float*)d_in[6];
    const float* fc2b = (const float*)d_in[7];
    const int*   src  = (const int*)d_in[8];
    const int*   dst  = (const int*)d_in[9];
    float* out = (float*)d_out;

    cudaFuncSetAttribute(k_gemm_tc, cudaFuncAttributeMaxDynamicSharedMemorySize,
                         SMEM_GEMM);

    k_csr<<<GG, 512>>>(src, dst);
    k_prepw<<<(LL * HH * 64 + 255) / 256, 256>>>(W);
    k_prepx<<<NV * 32 / 256, 256>>>(x);

    for (int l = 0; l < LL; l++) {
        k_spmm_bf<<<NV / 8, 256>>>(eps, l);
        k_gemm_tc<<<NV / 128, 256, SMEM_GEMM>>>(b, l);
    }

    k_sum<<<GG * 8, 64>>>();
    k_fc<<<GG, 128>>>(fc1w, fc1b, fc2w, fc2b, out);
}